// round 1
// baseline (speedup 1.0000x reference)
#include <cuda_runtime.h>
#include <cstdint>

#define NSTATE 768
#define BSZ 2
#define SEQ 2048
#define NTOK (BSZ*SEQ)        // 4096
#define NHEAD 12
#define DHEAD 64
#define MSLOTS 100

// ---------------- scratch (device globals; no allocations allowed) ----------------
__device__ float g_qkv[NTOK * 3 * NSTATE];     // [4096, 2304]
__device__ float g_mkv[MSLOTS * 2 * NSTATE];   // [100, 1536]
__device__ float g_a   [NTOK * NSTATE];        // self-attn out
__device__ float g_a1  [NTOK * NSTATE];        // memory-attn out
__device__ float g_fused[NTOK * NSTATE];       // gated fusion

// ---------------- generic 128x128x16 fp32 GEMM, 256 threads, 8x8 micro-tile -------
// MODE 0: C = A@B + bias
// MODE 1: A = concat(A, A2) along K (split at ksplit); epilogue:
//         al = sigmoid(acc + bias); C = al*ea + (1-al)*eb   (N must be 768 layout)
template<int MODE>
__global__ __launch_bounds__(256)
void gemm128(const float* __restrict__ A, const float* __restrict__ A2,
             const float* __restrict__ B, const float* __restrict__ bias,
             float* __restrict__ C,
             const float* __restrict__ ea, const float* __restrict__ eb,
             int M, int N, int K, int lda, int ksplit)
{
    __shared__ float Ast[16][132];   // [k][m], transposed A tile
    __shared__ float Bs [16][132];   // [k][n]

    const int tid = threadIdx.x;
    const int tx = tid & 15, ty = tid >> 4;
    const int row0 = blockIdx.y * 128;
    const int col0 = blockIdx.x * 128;
    const int T = K >> 4;

    int arow[2], aseg[2], bkk[2], bseg[2];
    #pragma unroll
    for (int i = 0; i < 2; i++) {
        int v = tid + i * 256;
        arow[i] = v >> 2;  aseg[i] = v & 3;
        bkk[i]  = v >> 5;  bseg[i] = v & 31;
    }

    float4 pa[2], pb[2];

    auto ldA = [&](int t, int i) {
        int grow = row0 + arow[i];
        int gk = t * 16 + aseg[i] * 4;
        if (grow < M) {
            const float* src;
            if (MODE == 1 && gk >= ksplit) src = A2 + (size_t)grow * lda + (gk - ksplit);
            else                           src = A  + (size_t)grow * lda + gk;
            pa[i] = *(const float4*)src;
        } else {
            pa[i] = make_float4(0.f, 0.f, 0.f, 0.f);
        }
    };
    auto ldB = [&](int t, int i) {
        int gk = t * 16 + bkk[i];
        pb[i] = *(const float4*)(B + (size_t)gk * N + col0 + bseg[i] * 4);
    };

    ldA(0, 0); ldA(0, 1); ldB(0, 0); ldB(0, 1);

    float acc[8][8];
    #pragma unroll
    for (int i = 0; i < 8; i++)
        #pragma unroll
        for (int j = 0; j < 8; j++) acc[i][j] = 0.f;

    for (int t = 0; t < T; ++t) {
        #pragma unroll
        for (int i = 0; i < 2; i++) {
            Ast[aseg[i]*4+0][arow[i]] = pa[i].x;
            Ast[aseg[i]*4+1][arow[i]] = pa[i].y;
            Ast[aseg[i]*4+2][arow[i]] = pa[i].z;
            Ast[aseg[i]*4+3][arow[i]] = pa[i].w;
            *(float4*)&Bs[bkk[i]][bseg[i]*4] = pb[i];
        }
        __syncthreads();
        if (t + 1 < T) { ldA(t+1, 0); ldA(t+1, 1); ldB(t+1, 0); ldB(t+1, 1); }

        #pragma unroll
        for (int kk = 0; kk < 16; kk++) {
            float4 a0 = *(float4*)&Ast[kk][ty*8];
            float4 a1v= *(float4*)&Ast[kk][ty*8+4];
            float4 b0 = *(float4*)&Bs [kk][tx*8];
            float4 b1v= *(float4*)&Bs [kk][tx*8+4];
            float af[8] = {a0.x,a0.y,a0.z,a0.w,a1v.x,a1v.y,a1v.z,a1v.w};
            float bf[8] = {b0.x,b0.y,b0.z,b0.w,b1v.x,b1v.y,b1v.z,b1v.w};
            #pragma unroll
            for (int i = 0; i < 8; i++)
                #pragma unroll
                for (int j = 0; j < 8; j++)
                    acc[i][j] = fmaf(af[i], bf[j], acc[i][j]);
        }
        __syncthreads();
    }

    #pragma unroll
    for (int i = 0; i < 8; i++) {
        int row = row0 + ty*8 + i;
        if (row >= M) continue;
        #pragma unroll
        for (int j4 = 0; j4 < 2; j4++) {
            int col = col0 + tx*8 + j4*4;
            float4 bv = *(const float4*)(bias + col);
            float4 r;
            r.x = acc[i][j4*4+0] + bv.x;
            r.y = acc[i][j4*4+1] + bv.y;
            r.z = acc[i][j4*4+2] + bv.z;
            r.w = acc[i][j4*4+3] + bv.w;
            size_t idx = (size_t)row * N + col;
            if (MODE == 1) {
                float4 av  = *(const float4*)(ea + idx);
                float4 a1x = *(const float4*)(eb + idx);
                float4 o;
                float al;
                al = 1.f/(1.f + __expf(-r.x)); o.x = a1x.x + al*(av.x - a1x.x);
                al = 1.f/(1.f + __expf(-r.y)); o.y = a1x.y + al*(av.y - a1x.y);
                al = 1.f/(1.f + __expf(-r.z)); o.z = a1x.z + al*(av.z - a1x.z);
                al = 1.f/(1.f + __expf(-r.w)); o.w = a1x.w + al*(av.w - a1x.w);
                *(float4*)(C + idx) = o;
            } else {
                *(float4*)(C + idx) = r;
            }
        }
    }
}

// ---------------- flash-style attention, 64 queries x 64-key blocks ----------------
// q from qkv buffer (stride q_stride), k/v with stride kv_stride. Online softmax,
// NO 1/sqrt(d) scaling (matches reference). out is [B, SEQ, NSTATE] layout.
__global__ __launch_bounds__(256)
void attn64(const float* __restrict__ qbase, const float* __restrict__ kbase,
            const float* __restrict__ vbase, float* __restrict__ outbuf,
            int kv_len, int q_stride, int kv_stride,
            long long q_bstride, long long kv_bstride)
{
    extern __shared__ float sm[];
    float* Qt = sm;               // [64 d][65]   Qt[d*65 + r]
    float* Kt = sm + 64*65;       // [64 d][65]   Kt[d*65 + c]
    float* Vs = sm + 2*64*65;     // [64 kc][65]  Vs[kc*65 + d]
    float* Ps = sm + 3*64*65;     // [64 q][65]   reductions + P tile

    const int tid = threadIdx.x;
    const int tx = tid & 15, ty = tid >> 4;
    const int h = blockIdx.y, b = blockIdx.z;
    const float* qb = qbase + (size_t)b * q_bstride  + h * 64;
    const float* kb = kbase + (size_t)b * kv_bstride + h * 64;
    const float* vb = vbase + (size_t)b * kv_bstride + h * 64;
    const int q0 = blockIdx.x * 64;

    // load Q tile transposed
    #pragma unroll
    for (int i = 0; i < 4; i++) {
        int v = tid + i * 256;
        int r = v >> 4, ds = v & 15;
        float4 qv = *(const float4*)(qb + (size_t)(q0 + r) * q_stride + ds * 4);
        Qt[(ds*4+0)*65 + r] = qv.x;
        Qt[(ds*4+1)*65 + r] = qv.y;
        Qt[(ds*4+2)*65 + r] = qv.z;
        Qt[(ds*4+3)*65 + r] = qv.w;
    }

    float m[4], l[4], o[4][4];
    #pragma unroll
    for (int i = 0; i < 4; i++) {
        m[i] = -1e30f; l[i] = 0.f;
        #pragma unroll
        for (int j = 0; j < 4; j++) o[i][j] = 0.f;
    }

    const int nkb = (kv_len + 63) >> 6;
    for (int t = 0; t < nkb; ++t) {
        __syncthreads();   // protect Kt/Vs/Ps from previous iteration's readers
        #pragma unroll
        for (int i = 0; i < 4; i++) {
            int v = tid + i * 256;
            int r = v >> 4, ds = v & 15;
            int kr = t * 64 + r;
            float4 kv4, vv4;
            if (kr < kv_len) {
                kv4 = *(const float4*)(kb + (size_t)kr * kv_stride + ds * 4);
                vv4 = *(const float4*)(vb + (size_t)kr * kv_stride + ds * 4);
            } else {
                kv4 = make_float4(0.f,0.f,0.f,0.f);
                vv4 = make_float4(0.f,0.f,0.f,0.f);
            }
            Kt[(ds*4+0)*65 + r] = kv4.x; Kt[(ds*4+1)*65 + r] = kv4.y;
            Kt[(ds*4+2)*65 + r] = kv4.z; Kt[(ds*4+3)*65 + r] = kv4.w;
            Vs[r*65 + ds*4+0] = vv4.x; Vs[r*65 + ds*4+1] = vv4.y;
            Vs[r*65 + ds*4+2] = vv4.z; Vs[r*65 + ds*4+3] = vv4.w;
        }
        __syncthreads();

        // S = Q K^T  (rows ty*4+i, cols tx*4+j)
        float s[4][4];
        #pragma unroll
        for (int i = 0; i < 4; i++)
            #pragma unroll
            for (int j = 0; j < 4; j++) s[i][j] = 0.f;
        #pragma unroll 8
        for (int kk = 0; kk < 64; kk++) {
            float qf[4], kf[4];
            #pragma unroll
            for (int i = 0; i < 4; i++) qf[i] = Qt[kk*65 + ty*4 + i];
            #pragma unroll
            for (int j = 0; j < 4; j++) kf[j] = Kt[kk*65 + tx*4 + j];
            #pragma unroll
            for (int i = 0; i < 4; i++)
                #pragma unroll
                for (int j = 0; j < 4; j++)
                    s[i][j] = fmaf(qf[i], kf[j], s[i][j]);
        }

        // mask out-of-range keys (only for last partial block)
        if ((t + 1) * 64 > kv_len) {
            #pragma unroll
            for (int j = 0; j < 4; j++)
                if (t * 64 + tx*4 + j >= kv_len) {
                    #pragma unroll
                    for (int i = 0; i < 4; i++) s[i][j] = -1e30f;
                }
        }

        // row max (16-partial reduce through shared)
        float lm[4];
        #pragma unroll
        for (int i = 0; i < 4; i++) {
            lm[i] = fmaxf(fmaxf(s[i][0], s[i][1]), fmaxf(s[i][2], s[i][3]));
            Ps[(ty*4+i)*65 + tx] = lm[i];
        }
        __syncthreads();
        float mn[4], sc[4];
        #pragma unroll
        for (int i = 0; i < 4; i++) {
            float rm = -1e30f;
            #pragma unroll
            for (int u = 0; u < 16; u++) rm = fmaxf(rm, Ps[(ty*4+i)*65 + u]);
            mn[i] = fmaxf(m[i], rm);
            sc[i] = __expf(m[i] - mn[i]);
            m[i] = mn[i];
        }
        float p[4][4], ls[4];
        #pragma unroll
        for (int i = 0; i < 4; i++) {
            ls[i] = 0.f;
            #pragma unroll
            for (int j = 0; j < 4; j++) {
                p[i][j] = __expf(s[i][j] - mn[i]);
                ls[i] += p[i][j];
            }
        }
        __syncthreads();   // all max reads done
        #pragma unroll
        for (int i = 0; i < 4; i++) Ps[(ty*4+i)*65 + tx] = ls[i];
        __syncthreads();
        #pragma unroll
        for (int i = 0; i < 4; i++) {
            float rs = 0.f;
            #pragma unroll
            for (int u = 0; u < 16; u++) rs += Ps[(ty*4+i)*65 + u];
            l[i] = l[i] * sc[i] + rs;
            #pragma unroll
            for (int j = 0; j < 4; j++) o[i][j] *= sc[i];
        }
        __syncthreads();   // all sum reads done before P overwrite
        #pragma unroll
        for (int i = 0; i < 4; i++)
            #pragma unroll
            for (int j = 0; j < 4; j++)
                Ps[(ty*4+i)*65 + tx*4 + j] = p[i][j];
        __syncthreads();

        // O += P V  (dims tx*4+j)
        #pragma unroll 8
        for (int kc = 0; kc < 64; kc++) {
            float pf[4], vf[4];
            #pragma unroll
            for (int i = 0; i < 4; i++) pf[i] = Ps[(ty*4+i)*65 + kc];
            #pragma unroll
            for (int j = 0; j < 4; j++) vf[j] = Vs[kc*65 + tx*4 + j];
            #pragma unroll
            for (int i = 0; i < 4; i++)
                #pragma unroll
                for (int j = 0; j < 4; j++)
                    o[i][j] = fmaf(pf[i], vf[j], o[i][j]);
        }
    }

    #pragma unroll
    for (int i = 0; i < 4; i++) {
        float inv = 1.f / l[i];
        int qrow = q0 + ty*4 + i;
        float4 r;
        r.x = o[i][0]*inv; r.y = o[i][1]*inv; r.z = o[i][2]*inv; r.w = o[i][3]*inv;
        *(float4*)(outbuf + ((size_t)b * SEQ + qrow) * NSTATE + h * 64 + tx * 4) = r;
    }
}

// ------------------------------- launch --------------------------------------------
extern "C" void kernel_launch(void* const* d_in, const int* in_sizes, int n_in,
                              void* d_out, int out_size)
{
    const float* x       = (const float*)d_in[0];
    const float* w_attn  = (const float*)d_in[1];
    const float* b_attn  = (const float*)d_in[2];
    const float* w_proj  = (const float*)d_in[3];
    const float* b_proj  = (const float*)d_in[4];
    const float* w_mem   = (const float*)d_in[5];
    const float* b_mem   = (const float*)d_in[6];
    const float* w_alpha = (const float*)d_in[7];
    const float* b_alpha = (const float*)d_in[8];
    const float* memf    = (const float*)d_in[9];
    float* out = (float*)d_out;

    float *qkv, *mkv, *a, *a1, *fu;
    cudaGetSymbolAddress((void**)&qkv, g_qkv);
    cudaGetSymbolAddress((void**)&mkv, g_mkv);
    cudaGetSymbolAddress((void**)&a,   g_a);
    cudaGetSymbolAddress((void**)&a1,  g_a1);
    cudaGetSymbolAddress((void**)&fu,  g_fused);

    const int smem = 4 * 64 * 65 * 4;   // 66560 B
    cudaFuncSetAttribute(attn64, cudaFuncAttributeMaxDynamicSharedMemorySize, smem);

    // 1) qkv = x @ w_attn + b_attn            [4096, 2304]
    gemm128<0><<<dim3(3*NSTATE/128, NTOK/128), 256>>>(
        x, nullptr, w_attn, b_attn, qkv, nullptr, nullptr,
        NTOK, 3*NSTATE, NSTATE, NSTATE, 0);

    // 2) mkv = mem @ w_mem + b_mem            [100, 1536] (batch-invariant)
    gemm128<0><<<dim3(2*NSTATE/128, 1), 256>>>(
        memf, nullptr, w_mem, b_mem, mkv, nullptr, nullptr,
        MSLOTS, 2*NSTATE, NSTATE, NSTATE, 0);

    // 3) self attention -> g_a
    attn64<<<dim3(SEQ/64, NHEAD, BSZ), 256, smem>>>(
        qkv, qkv + NSTATE, qkv + 2*NSTATE, a,
        SEQ, 3*NSTATE, 3*NSTATE,
        (long long)SEQ * 3 * NSTATE, (long long)SEQ * 3 * NSTATE);

    // 4) memory attention -> g_a1 (kv shared across batch)
    attn64<<<dim3(SEQ/64, NHEAD, BSZ), 256, smem>>>(
        qkv, mkv, mkv + NSTATE, a1,
        MSLOTS, 3*NSTATE, 2*NSTATE,
        (long long)SEQ * 3 * NSTATE, 0LL);

    // 5) alpha = sigmoid([a|a1] @ w_alpha + b_alpha); fused = alpha*a + (1-alpha)*a1
    gemm128<1><<<dim3(NSTATE/128, NTOK/128), 256>>>(
        a, a1, w_alpha, b_alpha, fu, a, a1,
        NTOK, NSTATE, 2*NSTATE, NSTATE, NSTATE);

    // 6) out = fused @ w_proj + b_proj
    gemm128<0><<<dim3(NSTATE/128, NTOK/128), 256>>>(
        fu, nullptr, w_proj, b_proj, out, nullptr, nullptr,
        NTOK, NSTATE, NSTATE, NSTATE, 0);
}

// round 3
// speedup vs baseline: 1.4922x; 1.4922x over previous
#include <cuda_runtime.h>
#include <cstdint>

#define NSTATE 768
#define BSZ 2
#define SEQ 2048
#define NTOK (BSZ*SEQ)        // 4096
#define NHEAD 12
#define DHEAD 64
#define MSLOTS 100

// ---------------- scratch (device globals; no allocations allowed) ----------------
__device__ float g_qkv[NTOK * 3 * NSTATE];     // [4096, 2304]
__device__ float g_mkv[MSLOTS * 2 * NSTATE];   // [100, 1536]
__device__ float g_a   [NTOK * NSTATE];        // self-attn out
__device__ float g_a1  [NTOK * NSTATE];        // memory-attn out
__device__ float g_fused[NTOK * NSTATE];       // gated fusion
// transposed weights (K-major, N-major rows: Bt[n][k])
__device__ float g_wattnT [3*NSTATE*NSTATE];   // [2304][768]
__device__ float g_wmemT  [2*NSTATE*NSTATE];   // [1536][768]
__device__ float g_walphaT[NSTATE*2*NSTATE];   // [768][1536]
__device__ float g_wprojT [NSTATE*NSTATE];     // [768][768]

// =================== PTX helpers (compute_103-safe only) ===================
__device__ __forceinline__ uint32_t smem_u32(const void* p){
    uint32_t a;
    asm("{ .reg .u64 t; cvta.to.shared.u64 t, %1; cvt.u32.u64 %0, t; }" : "=r"(a) : "l"(p));
    return a;
}
__device__ __forceinline__ void cp16(uint32_t dst, const float* src, bool v){
    int sz = v ? 16 : 0;
    asm volatile("cp.async.cg.shared.global [%0], [%1], 16, %2;" :: "r"(dst), "l"(src), "r"(sz));
}
template<int N> __device__ __forceinline__ void cp_wait(){
    asm volatile("cp.async.wait_group %0;" :: "n"(N) : "memory");
}
__device__ __forceinline__ void cp_commit(){
    asm volatile("cp.async.commit_group;" ::: "memory");
}
__device__ __forceinline__ uint32_t f2tf32(float f){
    uint32_t r;
    asm("cvt.rna.tf32.f32 %0, %1;" : "=r"(r) : "f"(f));
    return r;
}
__device__ __forceinline__ void mma_tf32(float* d, const uint32_t* a, const uint32_t* b){
    asm volatile("mma.sync.aligned.m16n8k8.row.col.f32.tf32.tf32.f32 "
        "{%0,%1,%2,%3}, {%4,%5,%6,%7}, {%8,%9}, {%0,%1,%2,%3};"
        : "+f"(d[0]), "+f"(d[1]), "+f"(d[2]), "+f"(d[3])
        : "r"(a[0]), "r"(a[1]), "r"(a[2]), "r"(a[3]), "r"(b[0]), "r"(b[1]));
}

// =================== weight transpose: src[K][N] -> dst[N][K] (dims % 32 == 0) ===================
__global__ __launch_bounds__(256)
void transpose_k(const float* __restrict__ src, float* __restrict__ dst, int K, int N)
{
    __shared__ float tile[32][33];
    const int tx = threadIdx.x, ty = threadIdx.y;
    const int n0 = blockIdx.x * 32, k0 = blockIdx.y * 32;
    #pragma unroll
    for (int r = 0; r < 4; r++)
        tile[ty + r*8][tx] = src[(size_t)(k0 + ty + r*8) * N + n0 + tx];
    __syncthreads();
    #pragma unroll
    for (int r = 0; r < 4; r++)
        dst[(size_t)(n0 + ty + r*8) * K + k0 + tx] = tile[tx][ty + r*8];
}

// =================== mma.sync tf32 GEMM: C[M,N] = A[M,K] @ Bt^T + bias ===================
// Bt is [N][K] row-major (pre-transposed weight). BM=BN=128, BK=32.
// 8 warps as 2(m) x 4(n); warp computes 64x32 via 4x4 m16n8k8 tiles.
// MODE 0: C = A@B + bias
// MODE 1: A = concat(A,A2) along K at ksplit; C = eb + sigmoid(acc+bias)*(ea-eb)
// smem: A0 @0, A1 @18432, B0 @36864, B1 @55296 (each 128 rows x 36 floats = 18432B).
// Epilogue stage (128x132 floats) reuses the same allocation.
template<int MODE>
__global__ __launch_bounds__(256)
void gemm_mma(const float* __restrict__ A, const float* __restrict__ A2,
              const float* __restrict__ Bt, const float* __restrict__ bias,
              float* __restrict__ C, const float* __restrict__ ea, const float* __restrict__ eb,
              int M, int N, int K, int lda, int ksplit)
{
    extern __shared__ char smem[];
    const uint32_t sb = smem_u32(smem);
    const int tid = threadIdx.x;
    const int w = tid >> 5, lane = tid & 31;
    const int lr = lane >> 2, kc = lane & 3;
    const int warp_m = (w >> 2) * 64;
    const int warp_n = (w & 3) * 32;
    const int row0 = blockIdx.y * 128, col0 = blockIdx.x * 128;

    const int T = K >> 5;                    // K-blocks of 32
    const int lrow = tid >> 1;               // 0..127 (tile row for A; tile n for B)
    const int c16b = (tid & 1) * 4;          // first 16B-chunk index (of 8 per row)
    const bool aval = (row0 + lrow) < M;

    auto load_chunk = [&](int t, int b){
        int k0 = t * 32;
        const float* As; int ka;
        if (MODE == 1 && k0 >= ksplit) { As = A2; ka = k0 - ksplit; } else { As = A; ka = k0; }
        const float* asrc = As + (size_t)(row0 + lrow) * lda + ka;
        const float* bsrc = Bt + (size_t)(col0 + lrow) * K + k0;
        uint32_t da = sb + (uint32_t)b * 18432u;
        uint32_t db = sb + 36864u + (uint32_t)b * 18432u;
        #pragma unroll
        for (int j = 0; j < 4; j++) {
            uint32_t off = (uint32_t)lrow * 144u + (uint32_t)(c16b + j) * 16u;
            cp16(da + off, asrc + (c16b + j) * 4, aval);
            cp16(db + off, bsrc + (c16b + j) * 4, true);
        }
        cp_commit();
    };

    float acc[4][4][4];
    #pragma unroll
    for (int i = 0; i < 4; i++)
        #pragma unroll
        for (int j = 0; j < 4; j++)
            #pragma unroll
            for (int r = 0; r < 4; r++) acc[i][j][r] = 0.f;

    load_chunk(0, 0);

    for (int t = 0; t < T; ++t) {
        int b = t & 1;
        if (t + 1 < T) { load_chunk(t + 1, b ^ 1); cp_wait<1>(); }
        else           { cp_wait<0>(); }
        __syncthreads();

        const float* Asb = (const float*)smem + b * 4608;           // 128*36
        const float* Bsb = (const float*)smem + 9216 + b * 4608;
        #pragma unroll
        for (int ks = 0; ks < 4; ks++) {
            const int kbase = ks * 8 + kc;
            uint32_t af[4][4], bf[4][2];
            #pragma unroll
            for (int i = 0; i < 4; i++) {
                int r0 = (warp_m + i * 16 + lr) * 36;
                af[i][0] = f2tf32(Asb[r0 + kbase]);
                af[i][1] = f2tf32(Asb[r0 + 8*36 + kbase]);
                af[i][2] = f2tf32(Asb[r0 + kbase + 4]);
                af[i][3] = f2tf32(Asb[r0 + 8*36 + kbase + 4]);
            }
            #pragma unroll
            for (int j = 0; j < 4; j++) {
                int r0 = (warp_n + j * 8 + lr) * 36;
                bf[j][0] = f2tf32(Bsb[r0 + kbase]);
                bf[j][1] = f2tf32(Bsb[r0 + kbase + 4]);
            }
            #pragma unroll
            for (int i = 0; i < 4; i++)
                #pragma unroll
                for (int j = 0; j < 4; j++)
                    mma_tf32(acc[i][j], af[i], bf[j]);
        }
        __syncthreads();
    }

    // ---- epilogue: regs -> smem stage -> coalesced STG with bias / gate ----
    float* st = (float*)smem;    // 128 x 132 floats
    #pragma unroll
    for (int i = 0; i < 4; i++) {
        #pragma unroll
        for (int j = 0; j < 4; j++) {
            int row = warp_m + i * 16 + lr;
            int col = warp_n + j * 8 + 2 * kc;
            *(float2*)&st[row * 132 + col]       = make_float2(acc[i][j][0], acc[i][j][1]);
            *(float2*)&st[(row + 8) * 132 + col] = make_float2(acc[i][j][2], acc[i][j][3]);
        }
    }
    __syncthreads();
    {
        int r  = tid >> 1;
        int ch = (tid & 1) * 64;
        int grow = row0 + r;
        if (grow < M) {
            #pragma unroll
            for (int c4 = 0; c4 < 16; c4++) {
                int col = ch + c4 * 4;
                float4 v  = *(float4*)&st[r * 132 + col];
                float4 bv = *(const float4*)(bias + col0 + col);
                v.x += bv.x; v.y += bv.y; v.z += bv.z; v.w += bv.w;
                size_t idx = (size_t)grow * N + col0 + col;
                if (MODE == 1) {
                    float4 av  = *(const float4*)(ea + idx);
                    float4 a1v = *(const float4*)(eb + idx);
                    float4 o; float al;
                    al = 1.f/(1.f + __expf(-v.x)); o.x = a1v.x + al*(av.x - a1v.x);
                    al = 1.f/(1.f + __expf(-v.y)); o.y = a1v.y + al*(av.y - a1v.y);
                    al = 1.f/(1.f + __expf(-v.z)); o.z = a1v.z + al*(av.z - a1v.z);
                    al = 1.f/(1.f + __expf(-v.w)); o.w = a1v.w + al*(av.w - a1v.w);
                    *(float4*)(C + idx) = o;
                } else {
                    *(float4*)(C + idx) = v;
                }
            }
        }
    }
}

// ---------------- flash-style attention, 64 queries x 64-key blocks ----------------
// Vectorized LDS (pad 68 for 16B alignment). NO 1/sqrt(d) scaling (matches reference).
#define APAD 68
__global__ __launch_bounds__(256)
void attn64(const float* __restrict__ qbase, const float* __restrict__ kbase,
            const float* __restrict__ vbase, float* __restrict__ outbuf,
            int kv_len, int q_stride, int kv_stride,
            long long q_bstride, long long kv_bstride)
{
    extern __shared__ float sm[];
    float* Qt = sm;                 // [64 d][APAD]   Qt[d*APAD + r]
    float* Kt = sm + 64*APAD;       // [64 d][APAD]   Kt[d*APAD + c]
    float* Vs = sm + 2*64*APAD;     // [64 kc][APAD]  Vs[kc*APAD + d]
    float* Ps = sm + 3*64*APAD;     // [64 q][APAD]   reductions + P tile

    const int tid = threadIdx.x;
    const int tx = tid & 15, ty = tid >> 4;
    const int h = blockIdx.y, b = blockIdx.z;
    const float* qb = qbase + (size_t)b * q_bstride  + h * 64;
    const float* kb = kbase + (size_t)b * kv_bstride + h * 64;
    const float* vb = vbase + (size_t)b * kv_bstride + h * 64;
    const int q0 = blockIdx.x * 64;

    // load Q tile transposed
    #pragma unroll
    for (int i = 0; i < 4; i++) {
        int v = tid + i * 256;
        int r = v >> 4, ds = v & 15;
        float4 qv = *(const float4*)(qb + (size_t)(q0 + r) * q_stride + ds * 4);
        Qt[(ds*4+0)*APAD + r] = qv.x;
        Qt[(ds*4+1)*APAD + r] = qv.y;
        Qt[(ds*4+2)*APAD + r] = qv.z;
        Qt[(ds*4+3)*APAD + r] = qv.w;
    }

    float m[4], l[4], o[4][4];
    #pragma unroll
    for (int i = 0; i < 4; i++) {
        m[i] = -1e30f; l[i] = 0.f;
        #pragma unroll
        for (int j = 0; j < 4; j++) o[i][j] = 0.f;
    }

    const int nkb = (kv_len + 63) >> 6;
    for (int t = 0; t < nkb; ++t) {
        __syncthreads();
        #pragma unroll
        for (int i = 0; i < 4; i++) {
            int v = tid + i * 256;
            int r = v >> 4, ds = v & 15;
            int kr = t * 64 + r;
            float4 kv4, vv4;
            if (kr < kv_len) {
                kv4 = *(const float4*)(kb + (size_t)kr * kv_stride + ds * 4);
                vv4 = *(const float4*)(vb + (size_t)kr * kv_stride + ds * 4);
            } else {
                kv4 = make_float4(0.f,0.f,0.f,0.f);
                vv4 = make_float4(0.f,0.f,0.f,0.f);
            }
            Kt[(ds*4+0)*APAD + r] = kv4.x; Kt[(ds*4+1)*APAD + r] = kv4.y;
            Kt[(ds*4+2)*APAD + r] = kv4.z; Kt[(ds*4+3)*APAD + r] = kv4.w;
            Vs[r*APAD + ds*4+0] = vv4.x; Vs[r*APAD + ds*4+1] = vv4.y;
            Vs[r*APAD + ds*4+2] = vv4.z; Vs[r*APAD + ds*4+3] = vv4.w;
        }
        __syncthreads();

        // S = Q K^T
        float s[4][4];
        #pragma unroll
        for (int i = 0; i < 4; i++)
            #pragma unroll
            for (int j = 0; j < 4; j++) s[i][j] = 0.f;
        #pragma unroll 8
        for (int kk = 0; kk < 64; kk++) {
            float4 qv = *(float4*)&Qt[kk*APAD + ty*4];
            float4 kv = *(float4*)&Kt[kk*APAD + tx*4];
            float qf[4] = {qv.x, qv.y, qv.z, qv.w};
            float kf[4] = {kv.x, kv.y, kv.z, kv.w};
            #pragma unroll
            for (int i = 0; i < 4; i++)
                #pragma unroll
                for (int j = 0; j < 4; j++)
                    s[i][j] = fmaf(qf[i], kf[j], s[i][j]);
        }

        if ((t + 1) * 64 > kv_len) {
            #pragma unroll
            for (int j = 0; j < 4; j++)
                if (t * 64 + tx*4 + j >= kv_len) {
                    #pragma unroll
                    for (int i = 0; i < 4; i++) s[i][j] = -1e30f;
                }
        }

        // row max
        float lm[4];
        #pragma unroll
        for (int i = 0; i < 4; i++) {
            lm[i] = fmaxf(fmaxf(s[i][0], s[i][1]), fmaxf(s[i][2], s[i][3]));
            Ps[(ty*4+i)*APAD + tx] = lm[i];
        }
        __syncthreads();
        float mn[4], sc[4];
        #pragma unroll
        for (int i = 0; i < 4; i++) {
            float rm = -1e30f;
            #pragma unroll
            for (int u = 0; u < 16; u++) rm = fmaxf(rm, Ps[(ty*4+i)*APAD + u]);
            mn[i] = fmaxf(m[i], rm);
            sc[i] = __expf(m[i] - mn[i]);
            m[i] = mn[i];
        }
        float p[4][4], ls[4];
        #pragma unroll
        for (int i = 0; i < 4; i++) {
            ls[i] = 0.f;
            #pragma unroll
            for (int j = 0; j < 4; j++) {
                p[i][j] = __expf(s[i][j] - mn[i]);
                ls[i] += p[i][j];
            }
        }
        __syncthreads();
        #pragma unroll
        for (int i = 0; i < 4; i++) Ps[(ty*4+i)*APAD + tx] = ls[i];
        __syncthreads();
        #pragma unroll
        for (int i = 0; i < 4; i++) {
            float rs = 0.f;
            #pragma unroll
            for (int u = 0; u < 16; u++) rs += Ps[(ty*4+i)*APAD + u];
            l[i] = l[i] * sc[i] + rs;
            #pragma unroll
            for (int j = 0; j < 4; j++) o[i][j] *= sc[i];
        }
        __syncthreads();
        #pragma unroll
        for (int i = 0; i < 4; i++)
            #pragma unroll
            for (int j = 0; j < 4; j++)
                Ps[(ty*4+i)*APAD + tx*4 + j] = p[i][j];
        __syncthreads();

        // O += P V  (vectorized: 4 kc at a time)
        #pragma unroll 4
        for (int kc4 = 0; kc4 < 16; kc4++) {
            float pr[4][4];
            #pragma unroll
            for (int i = 0; i < 4; i++)
                *(float4*)&pr[i][0] = *(float4*)&Ps[(ty*4+i)*APAD + kc4*4];
            #pragma unroll
            for (int jj = 0; jj < 4; jj++) {
                float4 vv = *(float4*)&Vs[(kc4*4+jj)*APAD + tx*4];
                float vf[4] = {vv.x, vv.y, vv.z, vv.w};
                #pragma unroll
                for (int i = 0; i < 4; i++)
                    #pragma unroll
                    for (int j = 0; j < 4; j++)
                        o[i][j] = fmaf(pr[i][jj], vf[j], o[i][j]);
            }
        }
    }

    #pragma unroll
    for (int i = 0; i < 4; i++) {
        float inv = 1.f / l[i];
        int qrow = q0 + ty*4 + i;
        float4 r;
        r.x = o[i][0]*inv; r.y = o[i][1]*inv; r.z = o[i][2]*inv; r.w = o[i][3]*inv;
        *(float4*)(outbuf + ((size_t)b * SEQ + qrow) * NSTATE + h * 64 + tx * 4) = r;
    }
}

// ------------------------------- launch --------------------------------------------
extern "C" void kernel_launch(void* const* d_in, const int* in_sizes, int n_in,
                              void* d_out, int out_size)
{
    const float* x       = (const float*)d_in[0];
    const float* w_attn  = (const float*)d_in[1];
    const float* b_attn  = (const float*)d_in[2];
    const float* w_proj  = (const float*)d_in[3];
    const float* b_proj  = (const float*)d_in[4];
    const float* w_mem   = (const float*)d_in[5];
    const float* b_mem   = (const float*)d_in[6];
    const float* w_alpha = (const float*)d_in[7];
    const float* b_alpha = (const float*)d_in[8];
    const float* memf    = (const float*)d_in[9];
    float* out = (float*)d_out;

    float *qkv, *mkv, *a, *a1, *fu, *wattnT, *wmemT, *walphaT, *wprojT;
    cudaGetSymbolAddress((void**)&qkv, g_qkv);
    cudaGetSymbolAddress((void**)&mkv, g_mkv);
    cudaGetSymbolAddress((void**)&a,   g_a);
    cudaGetSymbolAddress((void**)&a1,  g_a1);
    cudaGetSymbolAddress((void**)&fu,  g_fused);
    cudaGetSymbolAddress((void**)&wattnT,  g_wattnT);
    cudaGetSymbolAddress((void**)&wmemT,   g_wmemT);
    cudaGetSymbolAddress((void**)&walphaT, g_walphaT);
    cudaGetSymbolAddress((void**)&wprojT,  g_wprojT);

    const int attn_smem = 4 * 64 * APAD * 4;   // 69632
    const int gemm_smem = 73728;               // 4 x (128x36 floats)
    cudaFuncSetAttribute(attn64, cudaFuncAttributeMaxDynamicSharedMemorySize, attn_smem);
    cudaFuncSetAttribute(gemm_mma<0>, cudaFuncAttributeMaxDynamicSharedMemorySize, gemm_smem);
    cudaFuncSetAttribute(gemm_mma<1>, cudaFuncAttributeMaxDynamicSharedMemorySize, gemm_smem);

    dim3 tb(32, 8);
    // weight transposes: src[K][N] -> dst[N][K]
    transpose_k<<<dim3(3*NSTATE/32, NSTATE/32), tb>>>(w_attn,  wattnT,  NSTATE,   3*NSTATE);
    transpose_k<<<dim3(2*NSTATE/32, NSTATE/32), tb>>>(w_mem,   wmemT,   NSTATE,   2*NSTATE);
    transpose_k<<<dim3(NSTATE/32, 2*NSTATE/32), tb>>>(w_alpha, walphaT, 2*NSTATE, NSTATE);
    transpose_k<<<dim3(NSTATE/32, NSTATE/32),   tb>>>(w_proj,  wprojT,  NSTATE,   NSTATE);

    // 1) qkv = x @ w_attn + b_attn      [4096, 2304]
    gemm_mma<0><<<dim3(3*NSTATE/128, NTOK/128), 256, gemm_smem>>>(
        x, nullptr, wattnT, b_attn, qkv, nullptr, nullptr,
        NTOK, 3*NSTATE, NSTATE, NSTATE, 0);

    // 2) mkv = mem @ w_mem + b_mem      [100, 1536]
    gemm_mma<0><<<dim3(2*NSTATE/128, 1), 256, gemm_smem>>>(
        memf, nullptr, wmemT, b_mem, mkv, nullptr, nullptr,
        MSLOTS, 2*NSTATE, NSTATE, NSTATE, 0);

    // 3) self attention -> g_a
    attn64<<<dim3(SEQ/64, NHEAD, BSZ), 256, attn_smem>>>(
        qkv, qkv + NSTATE, qkv + 2*NSTATE, a,
        SEQ, 3*NSTATE, 3*NSTATE,
        (long long)SEQ * 3 * NSTATE, (long long)SEQ * 3 * NSTATE);

    // 4) memory attention -> g_a1 (kv shared across batch)
    attn64<<<dim3(SEQ/64, NHEAD, BSZ), 256, attn_smem>>>(
        qkv, mkv, mkv + NSTATE, a1,
        MSLOTS, 3*NSTATE, 2*NSTATE,
        (long long)SEQ * 3 * NSTATE, 0LL);

    // 5) fused = sigmoid([a|a1]@w_alpha + b_alpha) gate
    gemm_mma<1><<<dim3(NSTATE/128, NTOK/128), 256, gemm_smem>>>(
        a, a1, walphaT, b_alpha, fu, a, a1,
        NTOK, NSTATE, 2*NSTATE, NSTATE, NSTATE);

    // 6) out = fused @ w_proj + b_proj
    gemm_mma<0><<<dim3(NSTATE/128, NTOK/128), 256, gemm_smem>>>(
        fu, nullptr, wprojT, b_proj, out, nullptr, nullptr,
        NTOK, NSTATE, NSTATE, NSTATE, 0);
}

// round 4
// speedup vs baseline: 2.0434x; 1.3694x over previous
#include <cuda_runtime.h>
#include <cstdint>

#define NSTATE 768
#define BSZ 2
#define SEQ 2048
#define NTOK (BSZ*SEQ)        // 4096
#define NHEAD 12
#define DHEAD 64
#define MSLOTS 100

// ---------------- scratch (device globals; no allocations allowed) ----------------
__device__ float g_qkv[NTOK * 3 * NSTATE];     // [4096, 2304]
__device__ float g_mkv[MSLOTS * 2 * NSTATE];   // [100, 1536]
__device__ float g_a   [NTOK * NSTATE];        // self-attn out
__device__ float g_a1  [NTOK * NSTATE];        // memory-attn out
__device__ float g_fused[NTOK * NSTATE];       // gated fusion
// transposed weights (K-major, N-major rows: Bt[n][k])
__device__ float g_wattnT [3*NSTATE*NSTATE];   // [2304][768]
__device__ float g_wmemT  [2*NSTATE*NSTATE];   // [1536][768]
__device__ float g_walphaT[NSTATE*2*NSTATE];   // [768][1536]
__device__ float g_wprojT [NSTATE*NSTATE];     // [768][768]

// =================== PTX helpers (compute_103-safe only) ===================
__device__ __forceinline__ uint32_t smem_u32(const void* p){
    uint32_t a;
    asm("{ .reg .u64 t; cvta.to.shared.u64 t, %1; cvt.u32.u64 %0, t; }" : "=r"(a) : "l"(p));
    return a;
}
__device__ __forceinline__ void cp16(uint32_t dst, const float* src, bool v){
    int sz = v ? 16 : 0;
    asm volatile("cp.async.cg.shared.global [%0], [%1], 16, %2;" :: "r"(dst), "l"(src), "r"(sz));
}
template<int N> __device__ __forceinline__ void cp_wait(){
    asm volatile("cp.async.wait_group %0;" :: "n"(N) : "memory");
}
__device__ __forceinline__ void cp_commit(){
    asm volatile("cp.async.commit_group;" ::: "memory");
}
__device__ __forceinline__ uint32_t f2tf32(float f){
    uint32_t r;
    asm("cvt.rna.tf32.f32 %0, %1;" : "=r"(r) : "f"(f));
    return r;
}
__device__ __forceinline__ void split_tf32(float x, uint32_t& hi, uint32_t& lo){
    hi = f2tf32(x);
    lo = f2tf32(x - __uint_as_float(hi));
}
__device__ __forceinline__ void mma_tf32(float* d, const uint32_t* a, const uint32_t* b){
    asm volatile("mma.sync.aligned.m16n8k8.row.col.f32.tf32.tf32.f32 "
        "{%0,%1,%2,%3}, {%4,%5,%6,%7}, {%8,%9}, {%0,%1,%2,%3};"
        : "+f"(d[0]), "+f"(d[1]), "+f"(d[2]), "+f"(d[3])
        : "r"(a[0]), "r"(a[1]), "r"(a[2]), "r"(a[3]), "r"(b[0]), "r"(b[1]));
}

// =================== weight transpose: src[K][N] -> dst[N][K] (dims % 32 == 0) ===================
__global__ __launch_bounds__(256)
void transpose_k(const float* __restrict__ src, float* __restrict__ dst, int K, int N)
{
    __shared__ float tile[32][33];
    const int tx = threadIdx.x, ty = threadIdx.y;
    const int n0 = blockIdx.x * 32, k0 = blockIdx.y * 32;
    #pragma unroll
    for (int r = 0; r < 4; r++)
        tile[ty + r*8][tx] = src[(size_t)(k0 + ty + r*8) * N + n0 + tx];
    __syncthreads();
    #pragma unroll
    for (int r = 0; r < 4; r++)
        dst[(size_t)(n0 + ty + r*8) * K + k0 + tx] = tile[tx][ty + r*8];
}

// =================== mma.sync tf32 GEMM (unchanged from R3) ===================
template<int MODE>
__global__ __launch_bounds__(256)
void gemm_mma(const float* __restrict__ A, const float* __restrict__ A2,
              const float* __restrict__ Bt, const float* __restrict__ bias,
              float* __restrict__ C, const float* __restrict__ ea, const float* __restrict__ eb,
              int M, int N, int K, int lda, int ksplit)
{
    extern __shared__ char smem[];
    const uint32_t sb = smem_u32(smem);
    const int tid = threadIdx.x;
    const int w = tid >> 5, lane = tid & 31;
    const int lr = lane >> 2, kc = lane & 3;
    const int warp_m = (w >> 2) * 64;
    const int warp_n = (w & 3) * 32;
    const int row0 = blockIdx.y * 128, col0 = blockIdx.x * 128;

    const int T = K >> 5;
    const int lrow = tid >> 1;
    const int c16b = (tid & 1) * 4;
    const bool aval = (row0 + lrow) < M;

    auto load_chunk = [&](int t, int b){
        int k0 = t * 32;
        const float* As; int ka;
        if (MODE == 1 && k0 >= ksplit) { As = A2; ka = k0 - ksplit; } else { As = A; ka = k0; }
        const float* asrc = As + (size_t)(row0 + lrow) * lda + ka;
        const float* bsrc = Bt + (size_t)(col0 + lrow) * K + k0;
        uint32_t da = sb + (uint32_t)b * 18432u;
        uint32_t db = sb + 36864u + (uint32_t)b * 18432u;
        #pragma unroll
        for (int j = 0; j < 4; j++) {
            uint32_t off = (uint32_t)lrow * 144u + (uint32_t)(c16b + j) * 16u;
            cp16(da + off, asrc + (c16b + j) * 4, aval);
            cp16(db + off, bsrc + (c16b + j) * 4, true);
        }
        cp_commit();
    };

    float acc[4][4][4];
    #pragma unroll
    for (int i = 0; i < 4; i++)
        #pragma unroll
        for (int j = 0; j < 4; j++)
            #pragma unroll
            for (int r = 0; r < 4; r++) acc[i][j][r] = 0.f;

    load_chunk(0, 0);

    for (int t = 0; t < T; ++t) {
        int b = t & 1;
        if (t + 1 < T) { load_chunk(t + 1, b ^ 1); cp_wait<1>(); }
        else           { cp_wait<0>(); }
        __syncthreads();

        const float* Asb = (const float*)smem + b * 4608;
        const float* Bsb = (const float*)smem + 9216 + b * 4608;
        #pragma unroll
        for (int ks = 0; ks < 4; ks++) {
            const int kbase = ks * 8 + kc;
            uint32_t af[4][4], bf[4][2];
            #pragma unroll
            for (int i = 0; i < 4; i++) {
                int r0 = (warp_m + i * 16 + lr) * 36;
                af[i][0] = f2tf32(Asb[r0 + kbase]);
                af[i][1] = f2tf32(Asb[r0 + 8*36 + kbase]);
                af[i][2] = f2tf32(Asb[r0 + kbase + 4]);
                af[i][3] = f2tf32(Asb[r0 + 8*36 + kbase + 4]);
            }
            #pragma unroll
            for (int j = 0; j < 4; j++) {
                int r0 = (warp_n + j * 8 + lr) * 36;
                bf[j][0] = f2tf32(Bsb[r0 + kbase]);
                bf[j][1] = f2tf32(Bsb[r0 + kbase + 4]);
            }
            #pragma unroll
            for (int i = 0; i < 4; i++)
                #pragma unroll
                for (int j = 0; j < 4; j++)
                    mma_tf32(acc[i][j], af[i], bf[j]);
        }
        __syncthreads();
    }

    float* st = (float*)smem;    // 128 x 132 floats
    #pragma unroll
    for (int i = 0; i < 4; i++) {
        #pragma unroll
        for (int j = 0; j < 4; j++) {
            int row = warp_m + i * 16 + lr;
            int col = warp_n + j * 8 + 2 * kc;
            *(float2*)&st[row * 132 + col]       = make_float2(acc[i][j][0], acc[i][j][1]);
            *(float2*)&st[(row + 8) * 132 + col] = make_float2(acc[i][j][2], acc[i][j][3]);
        }
    }
    __syncthreads();
    {
        int r  = tid >> 1;
        int ch = (tid & 1) * 64;
        int grow = row0 + r;
        if (grow < M) {
            #pragma unroll
            for (int c4 = 0; c4 < 16; c4++) {
                int col = ch + c4 * 4;
                float4 v  = *(float4*)&st[r * 132 + col];
                float4 bv = *(const float4*)(bias + col0 + col);
                v.x += bv.x; v.y += bv.y; v.z += bv.z; v.w += bv.w;
                size_t idx = (size_t)grow * N + col0 + col;
                if (MODE == 1) {
                    float4 av  = *(const float4*)(ea + idx);
                    float4 a1v = *(const float4*)(eb + idx);
                    float4 o; float al;
                    al = 1.f/(1.f + __expf(-v.x)); o.x = a1v.x + al*(av.x - a1v.x);
                    al = 1.f/(1.f + __expf(-v.y)); o.y = a1v.y + al*(av.y - a1v.y);
                    al = 1.f/(1.f + __expf(-v.z)); o.z = a1v.z + al*(av.z - a1v.z);
                    al = 1.f/(1.f + __expf(-v.w)); o.w = a1v.w + al*(av.w - a1v.w);
                    *(float4*)(C + idx) = o;
                } else {
                    *(float4*)(C + idx) = v;
                }
            }
        }
    }
}

// =================== tensor-core flash attention, 3x-tf32 (numerically ~fp32) ===================
// 128 q-rows per block, 8 warps x 16 q-rows, 64-key chunks. NO 1/sqrt(d) scaling.
// K tiles pad 68 (banks 4*lr+kc), V tiles pad 72 (banks 8*kc+lr): conflict-free frag LDS.
#define KP 68
#define VP 72
__global__ __launch_bounds__(256, 1)
void attn_mma(const float* __restrict__ qbase, const float* __restrict__ kbase,
              const float* __restrict__ vbase, float* __restrict__ outbuf,
              int kv_len, int q_stride, int kv_stride,
              long long q_bstride, long long kv_bstride)
{
    extern __shared__ float sm[];
    float* Khi = sm;                       // [64][KP]
    float* Klo = sm + 64*KP;
    float* Vhi = sm + 2*64*KP;             // [64][VP]
    float* Vlo = sm + 2*64*KP + 64*VP;

    const int tid = threadIdx.x;
    const int w = tid >> 5, lane = tid & 31;
    const int lr = lane >> 2, kc = lane & 3;
    const int h = blockIdx.y, b = blockIdx.z;
    const int q0 = blockIdx.x * 128;
    const float* qb = qbase + (size_t)b * q_bstride  + h * 64;
    const float* kb = kbase + (size_t)b * kv_bstride + h * 64;
    const float* vb = vbase + (size_t)b * kv_bstride + h * 64;

    const int qrow0 = q0 + w * 16 + lr;    // thread owns rows qrow0, qrow0+8

    // persistent Q fragments (hi/lo split), 8 k-chunks covering d=64
    uint32_t Qh[8][4], Ql[8][4];
    #pragma unroll
    for (int c = 0; c < 8; c++) {
        int d0 = kc + c * 8;
        split_tf32(qb[(size_t)qrow0       * q_stride + d0    ], Qh[c][0], Ql[c][0]);
        split_tf32(qb[(size_t)(qrow0 + 8) * q_stride + d0    ], Qh[c][1], Ql[c][1]);
        split_tf32(qb[(size_t)qrow0       * q_stride + d0 + 4], Qh[c][2], Ql[c][2]);
        split_tf32(qb[(size_t)(qrow0 + 8) * q_stride + d0 + 4], Qh[c][3], Ql[c][3]);
    }

    float m0 = -1e30f, m1 = -1e30f, l0 = 0.f, l1 = 0.f;
    float O[8][4];
    #pragma unroll
    for (int d = 0; d < 8; d++) { O[d][0]=0.f; O[d][1]=0.f; O[d][2]=0.f; O[d][3]=0.f; }

    const int nkb = (kv_len + 63) >> 6;
    for (int t = 0; t < nkb; ++t) {
        __syncthreads();   // prior iter's frag reads done before overwrite
        // ---- load + split K,V tiles (zero-fill beyond kv_len) ----
        {
            int row = tid >> 2;
            int kg = t * 64 + row;
            bool vld = kg < kv_len;
            const float* ks = kb + (size_t)kg * kv_stride;
            const float* vs = vb + (size_t)kg * kv_stride;
            #pragma unroll
            for (int i = 0; i < 4; i++) {
                int c = ((tid & 3) + i * 4) * 4;     // d offset (float4)
                float4 kk = vld ? *(const float4*)(ks + c) : make_float4(0.f,0.f,0.f,0.f);
                float4 vv = vld ? *(const float4*)(vs + c) : make_float4(0.f,0.f,0.f,0.f);
                uint32_t h4[4], l4[4];
                split_tf32(kk.x, h4[0], l4[0]); split_tf32(kk.y, h4[1], l4[1]);
                split_tf32(kk.z, h4[2], l4[2]); split_tf32(kk.w, h4[3], l4[3]);
                *(uint4*)&Khi[row*KP + c] = make_uint4(h4[0],h4[1],h4[2],h4[3]);
                *(uint4*)&Klo[row*KP + c] = make_uint4(l4[0],l4[1],l4[2],l4[3]);
                split_tf32(vv.x, h4[0], l4[0]); split_tf32(vv.y, h4[1], l4[1]);
                split_tf32(vv.z, h4[2], l4[2]); split_tf32(vv.w, h4[3], l4[3]);
                *(uint4*)&Vhi[row*VP + c] = make_uint4(h4[0],h4[1],h4[2],h4[3]);
                *(uint4*)&Vlo[row*VP + c] = make_uint4(l4[0],l4[1],l4[2],l4[3]);
            }
        }
        __syncthreads();

        // ---- S = Q K^T (3x tf32) ----
        float sD[8][4];
        #pragma unroll
        for (int nt = 0; nt < 8; nt++) {
            float d4[4] = {0.f, 0.f, 0.f, 0.f};
            const float* khp = &Khi[(8*nt + lr) * KP + kc];
            const float* klp = &Klo[(8*nt + lr) * KP + kc];
            #pragma unroll
            for (int c = 0; c < 8; c++) {
                uint32_t bh[2], bl[2];
                bh[0] = __float_as_uint(khp[c*8]);     bh[1] = __float_as_uint(khp[c*8 + 4]);
                bl[0] = __float_as_uint(klp[c*8]);     bl[1] = __float_as_uint(klp[c*8 + 4]);
                mma_tf32(d4, Qh[c], bh);
                mma_tf32(d4, Qh[c], bl);
                mma_tf32(d4, Ql[c], bh);
            }
            sD[nt][0]=d4[0]; sD[nt][1]=d4[1]; sD[nt][2]=d4[2]; sD[nt][3]=d4[3];
        }

        // ---- mask partial chunk ----
        int rem = kv_len - t * 64;
        if (rem < 64) {
            #pragma unroll
            for (int nt = 0; nt < 8; nt++) {
                int k0e = 8*nt + 2*kc;
                if (k0e     >= rem) { sD[nt][0] = -1e30f; sD[nt][2] = -1e30f; }
                if (k0e + 1 >= rem) { sD[nt][1] = -1e30f; sD[nt][3] = -1e30f; }
            }
        }

        // ---- online softmax (register + quad-shfl) ----
        float rm0 = -1e30f, rm1 = -1e30f;
        #pragma unroll
        for (int nt = 0; nt < 8; nt++) {
            rm0 = fmaxf(rm0, fmaxf(sD[nt][0], sD[nt][1]));
            rm1 = fmaxf(rm1, fmaxf(sD[nt][2], sD[nt][3]));
        }
        rm0 = fmaxf(rm0, __shfl_xor_sync(0xffffffffu, rm0, 1));
        rm0 = fmaxf(rm0, __shfl_xor_sync(0xffffffffu, rm0, 2));
        rm1 = fmaxf(rm1, __shfl_xor_sync(0xffffffffu, rm1, 1));
        rm1 = fmaxf(rm1, __shfl_xor_sync(0xffffffffu, rm1, 2));
        float mn0 = fmaxf(m0, rm0), mn1 = fmaxf(m1, rm1);
        float sc0 = __expf(m0 - mn0), sc1 = __expf(m1 - mn1);
        m0 = mn0; m1 = mn1;
        float rs0 = 0.f, rs1 = 0.f;
        #pragma unroll
        for (int nt = 0; nt < 8; nt++) {
            sD[nt][0] = __expf(sD[nt][0] - m0);
            sD[nt][1] = __expf(sD[nt][1] - m0);
            sD[nt][2] = __expf(sD[nt][2] - m1);
            sD[nt][3] = __expf(sD[nt][3] - m1);
            rs0 += sD[nt][0] + sD[nt][1];
            rs1 += sD[nt][2] + sD[nt][3];
        }
        rs0 += __shfl_xor_sync(0xffffffffu, rs0, 1);
        rs0 += __shfl_xor_sync(0xffffffffu, rs0, 2);
        rs1 += __shfl_xor_sync(0xffffffffu, rs1, 1);
        rs1 += __shfl_xor_sync(0xffffffffu, rs1, 2);
        l0 = l0 * sc0 + rs0;
        l1 = l1 * sc1 + rs1;
        #pragma unroll
        for (int d = 0; d < 8; d++) {
            O[d][0] *= sc0; O[d][1] *= sc0; O[d][2] *= sc1; O[d][3] *= sc1;
        }

        // ---- O += P V (3x tf32); P permuted D->A layout via quad shfl ----
        const int s1 = (lane & ~3) | (kc >> 1);
        const int s2 = s1 + 2;
        #pragma unroll
        for (int c = 0; c < 8; c++) {
            float p0 = sD[c][0], p1 = sD[c][1], p2 = sD[c][2], p3 = sD[c][3];
            float e, o;
            e = __shfl_sync(0xffffffffu, p0, s1); o = __shfl_sync(0xffffffffu, p1, s1);
            float a0f = (kc & 1) ? o : e;                     // P[lr][key=kc]
            e = __shfl_sync(0xffffffffu, p2, s1); o = __shfl_sync(0xffffffffu, p3, s1);
            float a1f = (kc & 1) ? o : e;                     // P[lr+8][key=kc]
            e = __shfl_sync(0xffffffffu, p0, s2); o = __shfl_sync(0xffffffffu, p1, s2);
            float a2f = (kc & 1) ? o : e;                     // P[lr][key=kc+4]
            e = __shfl_sync(0xffffffffu, p2, s2); o = __shfl_sync(0xffffffffu, p3, s2);
            float a3f = (kc & 1) ? o : e;                     // P[lr+8][key=kc+4]
            uint32_t ah[4], al[4];
            split_tf32(a0f, ah[0], al[0]); split_tf32(a1f, ah[1], al[1]);
            split_tf32(a2f, ah[2], al[2]); split_tf32(a3f, ah[3], al[3]);
            const float* vhp = &Vhi[(8*c + kc) * VP + lr];
            const float* vlp = &Vlo[(8*c + kc) * VP + lr];
            #pragma unroll
            for (int dt = 0; dt < 8; dt++) {
                uint32_t bh[2], bl[2];
                bh[0] = __float_as_uint(vhp[dt*8]);          bh[1] = __float_as_uint(vhp[dt*8 + 4*VP]);
                bl[0] = __float_as_uint(vlp[dt*8]);          bl[1] = __float_as_uint(vlp[dt*8 + 4*VP]);
                mma_tf32(O[dt], ah, bh);
                mma_tf32(O[dt], ah, bl);
                mma_tf32(O[dt], al, bh);
            }
        }
    }

    // ---- epilogue ----
    float inv0 = 1.f / l0, inv1 = 1.f / l1;
    float* op0 = outbuf + ((size_t)b * SEQ + qrow0) * NSTATE + h * 64;
    float* op1 = op0 + 8 * NSTATE;
    #pragma unroll
    for (int dt = 0; dt < 8; dt++) {
        *(float2*)(op0 + dt*8 + 2*kc) = make_float2(O[dt][0]*inv0, O[dt][1]*inv0);
        *(float2*)(op1 + dt*8 + 2*kc) = make_float2(O[dt][2]*inv1, O[dt][3]*inv1);
    }
}

// ------------------------------- launch --------------------------------------------
extern "C" void kernel_launch(void* const* d_in, const int* in_sizes, int n_in,
                              void* d_out, int out_size)
{
    const float* x       = (const float*)d_in[0];
    const float* w_attn  = (const float*)d_in[1];
    const float* b_attn  = (const float*)d_in[2];
    const float* w_proj  = (const float*)d_in[3];
    const float* b_proj  = (const float*)d_in[4];
    const float* w_mem   = (const float*)d_in[5];
    const float* b_mem   = (const float*)d_in[6];
    const float* w_alpha = (const float*)d_in[7];
    const float* b_alpha = (const float*)d_in[8];
    const float* memf    = (const float*)d_in[9];
    float* out = (float*)d_out;

    float *qkv, *mkv, *a, *a1, *fu, *wattnT, *wmemT, *walphaT, *wprojT;
    cudaGetSymbolAddress((void**)&qkv, g_qkv);
    cudaGetSymbolAddress((void**)&mkv, g_mkv);
    cudaGetSymbolAddress((void**)&a,   g_a);
    cudaGetSymbolAddress((void**)&a1,  g_a1);
    cudaGetSymbolAddress((void**)&fu,  g_fused);
    cudaGetSymbolAddress((void**)&wattnT,  g_wattnT);
    cudaGetSymbolAddress((void**)&wmemT,   g_wmemT);
    cudaGetSymbolAddress((void**)&walphaT, g_walphaT);
    cudaGetSymbolAddress((void**)&wprojT,  g_wprojT);

    const int attn_smem = (2*64*KP + 2*64*VP) * 4;   // 71680
    const int gemm_smem = 73728;
    cudaFuncSetAttribute(attn_mma, cudaFuncAttributeMaxDynamicSharedMemorySize, attn_smem);
    cudaFuncSetAttribute(gemm_mma<0>, cudaFuncAttributeMaxDynamicSharedMemorySize, gemm_smem);
    cudaFuncSetAttribute(gemm_mma<1>, cudaFuncAttributeMaxDynamicSharedMemorySize, gemm_smem);

    dim3 tb(32, 8);
    transpose_k<<<dim3(3*NSTATE/32, NSTATE/32), tb>>>(w_attn,  wattnT,  NSTATE,   3*NSTATE);
    transpose_k<<<dim3(2*NSTATE/32, NSTATE/32), tb>>>(w_mem,   wmemT,   NSTATE,   2*NSTATE);
    transpose_k<<<dim3(NSTATE/32, 2*NSTATE/32), tb>>>(w_alpha, walphaT, 2*NSTATE, NSTATE);
    transpose_k<<<dim3(NSTATE/32, NSTATE/32),   tb>>>(w_proj,  wprojT,  NSTATE,   NSTATE);

    // 1) qkv = x @ w_attn + b_attn      [4096, 2304]
    gemm_mma<0><<<dim3(3*NSTATE/128, NTOK/128), 256, gemm_smem>>>(
        x, nullptr, wattnT, b_attn, qkv, nullptr, nullptr,
        NTOK, 3*NSTATE, NSTATE, NSTATE, 0);

    // 2) mkv = mem @ w_mem + b_mem      [100, 1536]
    gemm_mma<0><<<dim3(2*NSTATE/128, 1), 256, gemm_smem>>>(
        memf, nullptr, wmemT, b_mem, mkv, nullptr, nullptr,
        MSLOTS, 2*NSTATE, NSTATE, NSTATE, 0);

    // 3) self attention -> g_a
    attn_mma<<<dim3(SEQ/128, NHEAD, BSZ), 256, attn_smem>>>(
        qkv, qkv + NSTATE, qkv + 2*NSTATE, a,
        SEQ, 3*NSTATE, 3*NSTATE,
        (long long)SEQ * 3 * NSTATE, (long long)SEQ * 3 * NSTATE);

    // 4) memory attention -> g_a1 (kv shared across batch)
    attn_mma<<<dim3(SEQ/128, NHEAD, BSZ), 256, attn_smem>>>(
        qkv, mkv, mkv + NSTATE, a1,
        MSLOTS, 3*NSTATE, 2*NSTATE,
        (long long)SEQ * 3 * NSTATE, 0LL);

    // 5) fused = sigmoid([a|a1]@w_alpha + b_alpha) gate
    gemm_mma<1><<<dim3(NSTATE/128, NTOK/128), 256, gemm_smem>>>(
        a, a1, walphaT, b_alpha, fu, a, a1,
        NTOK, NSTATE, 2*NSTATE, NSTATE, NSTATE);

    // 6) out = fused @ w_proj + b_proj
    gemm_mma<0><<<dim3(NSTATE/128, NTOK/128), 256, gemm_smem>>>(
        fu, nullptr, wprojT, b_proj, out, nullptr, nullptr,
        NTOK, NSTATE, NSTATE, NSTATE, 0);
}

// round 7
// speedup vs baseline: 2.5571x; 1.2514x over previous
#include <cuda_runtime.h>
#include <cuda_fp16.h>
#include <cstdint>

#define NSTATE 768
#define BSZ 2
#define SEQ 2048
#define NTOK (BSZ*SEQ)        // 4096
#define NHEAD 12
#define DHEAD 64
#define MSLOTS 100

// ---------------- scratch (device globals; no allocations allowed) ----------------
__device__ float g_qkv[NTOK * 3 * NSTATE];     // [4096, 2304]
__device__ float g_mkv[MSLOTS * 2 * NSTATE];   // [100, 1536]
__device__ float g_a   [NTOK * NSTATE];        // self-attn out
__device__ float g_a1  [NTOK * NSTATE];        // memory-attn out
__device__ float g_fused[NTOK * NSTATE];       // gated fusion
// transposed weights (K-major, N-major rows: Bt[n][k])
__device__ float g_wattnT [3*NSTATE*NSTATE];   // [2304][768]
__device__ float g_wmemT  [2*NSTATE*NSTATE];   // [1536][768]
__device__ float g_walphaT[NSTATE*2*NSTATE];   // [768][1536]
__device__ float g_wprojT [NSTATE*NSTATE];     // [768][768]

// =================== helpers (compute_103-safe only) ===================
__device__ __forceinline__ uint32_t f2tf32(float f){
    uint32_t r;
    asm("cvt.rna.tf32.f32 %0, %1;" : "=r"(r) : "f"(f));
    return r;
}
__device__ __forceinline__ void mma_tf32(float* d, const uint32_t* a, const uint32_t* b){
    asm volatile("mma.sync.aligned.m16n8k8.row.col.f32.tf32.tf32.f32 "
        "{%0,%1,%2,%3}, {%4,%5,%6,%7}, {%8,%9}, {%0,%1,%2,%3};"
        : "+f"(d[0]), "+f"(d[1]), "+f"(d[2]), "+f"(d[3])
        : "r"(a[0]), "r"(a[1]), "r"(a[2]), "r"(a[3]), "r"(b[0]), "r"(b[1]));
}
__device__ __forceinline__ void mma_f16(float* d, const uint32_t* a, const uint32_t* b){
    asm volatile("mma.sync.aligned.m16n8k16.row.col.f32.f16.f16.f32 "
        "{%0,%1,%2,%3}, {%4,%5,%6,%7}, {%8,%9}, {%0,%1,%2,%3};"
        : "+f"(d[0]), "+f"(d[1]), "+f"(d[2]), "+f"(d[3])
        : "r"(a[0]), "r"(a[1]), "r"(a[2]), "r"(a[3]), "r"(b[0]), "r"(b[1]));
}
// split (x,y) into packed half2 hi and half2 lo (residual)
__device__ __forceinline__ void split2h(float x, float y, uint32_t& hi, uint32_t& lo){
    __half hx = __float2half_rn(x);
    __half hy = __float2half_rn(y);
    __half lx = __float2half_rn(x - __half2float(hx));
    __half ly = __float2half_rn(y - __half2float(hy));
    hi = (uint32_t)__half_as_ushort(hx) | ((uint32_t)__half_as_ushort(hy) << 16);
    lo = (uint32_t)__half_as_ushort(lx) | ((uint32_t)__half_as_ushort(ly) << 16);
}

// =================== weight transpose: src[K][N] -> dst[N][K] (dims % 32 == 0) ===================
__global__ __launch_bounds__(256)
void transpose_k(const float* __restrict__ src, float* __restrict__ dst, int K, int N)
{
    __shared__ float tile[32][33];
    const int tx = threadIdx.x, ty = threadIdx.y;
    const int n0 = blockIdx.x * 32, k0 = blockIdx.y * 32;
    #pragma unroll
    for (int r = 0; r < 4; r++)
        tile[ty + r*8][tx] = src[(size_t)(k0 + ty + r*8) * N + n0 + tx];
    __syncthreads();
    #pragma unroll
    for (int r = 0; r < 4; r++)
        dst[(size_t)(n0 + ty + r*8) * K + k0 + tx] = tile[tx][ty + r*8];
}

// =================== mma.sync tf32 GEMM, cvt hoisted to STS time ===================
// Bt is [N][K] row-major. BM=BN=128, BK=32. 8 warps 2(m)x4(n), warp 64x32, 4x4 m16n8k8.
// MODE 0: C = A@B + bias
// MODE 1: A = concat(A,A2) along K at ksplit; C = eb + sigmoid(acc+bias)*(ea-eb)
// smem words: A tiles at b*4608, B tiles at 9216 + b*4608 (rows of 36 words, tf32 bits).
template<int MODE>
__global__ __launch_bounds__(256)
void gemm_mma(const float* __restrict__ A, const float* __restrict__ A2,
              const float* __restrict__ Bt, const float* __restrict__ bias,
              float* __restrict__ C, const float* __restrict__ ea, const float* __restrict__ eb,
              int M, int N, int K, int lda, int ksplit)
{
    extern __shared__ char smem[];
    uint32_t* usm = (uint32_t*)smem;
    const int tid = threadIdx.x;
    const int w = tid >> 5, lane = tid & 31;
    const int lr = lane >> 2, kc = lane & 3;
    const int warp_m = (w >> 2) * 64;
    const int warp_n = (w & 3) * 32;
    const int row0 = blockIdx.y * 128, col0 = blockIdx.x * 128;

    const int T = K >> 5;
    const int arow = tid >> 1;           // 0..127
    const int acol0 = (tid & 1) * 16;    // 0 or 16 (floats)
    const bool aval = (row0 + arow) < M;

    float4 pa[4], pb[4];
    auto ldg = [&](int t){
        int k0 = t * 32;
        const float* As; int ka;
        if (MODE == 1 && k0 >= ksplit) { As = A2; ka = k0 - ksplit; } else { As = A; ka = k0; }
        const float* asrc = As + (size_t)(row0 + arow) * lda + ka + acol0;
        const float* bsrc = Bt + (size_t)(col0 + arow) * K + k0 + acol0;
        #pragma unroll
        for (int j = 0; j < 4; j++) {
            pa[j] = aval ? *(const float4*)(asrc + 4*j) : make_float4(0.f,0.f,0.f,0.f);
            pb[j] = *(const float4*)(bsrc + 4*j);
        }
    };
    auto sts = [&](int b){
        uint32_t* da = usm + b * 4608 + arow * 36 + acol0;
        uint32_t* db = usm + 9216 + b * 4608 + arow * 36 + acol0;
        #pragma unroll
        for (int j = 0; j < 4; j++) {
            *(uint4*)(da + 4*j) = make_uint4(f2tf32(pa[j].x), f2tf32(pa[j].y), f2tf32(pa[j].z), f2tf32(pa[j].w));
            *(uint4*)(db + 4*j) = make_uint4(f2tf32(pb[j].x), f2tf32(pb[j].y), f2tf32(pb[j].z), f2tf32(pb[j].w));
        }
    };

    float acc[4][4][4];
    #pragma unroll
    for (int i = 0; i < 4; i++)
        #pragma unroll
        for (int j = 0; j < 4; j++)
            #pragma unroll
            for (int r = 0; r < 4; r++) acc[i][j][r] = 0.f;

    ldg(0); sts(0);
    if (T > 1) ldg(1);
    __syncthreads();

    for (int t = 0; t < T; ++t) {
        int b = t & 1;
        const uint32_t* Asb = usm + b * 4608;
        const uint32_t* Bsb = usm + 9216 + b * 4608;
        #pragma unroll
        for (int ks = 0; ks < 4; ks++) {
            const int kbase = ks * 8 + kc;
            uint32_t af[4][4], bf[4][2];
            #pragma unroll
            for (int i = 0; i < 4; i++) {
                int r0 = (warp_m + i * 16 + lr) * 36;
                af[i][0] = Asb[r0 + kbase];
                af[i][1] = Asb[r0 + 8*36 + kbase];
                af[i][2] = Asb[r0 + kbase + 4];
                af[i][3] = Asb[r0 + 8*36 + kbase + 4];
            }
            #pragma unroll
            for (int j = 0; j < 4; j++) {
                int r0 = (warp_n + j * 8 + lr) * 36;
                bf[j][0] = Bsb[r0 + kbase];
                bf[j][1] = Bsb[r0 + kbase + 4];
            }
            #pragma unroll
            for (int i = 0; i < 4; i++)
                #pragma unroll
                for (int j = 0; j < 4; j++)
                    mma_tf32(acc[i][j], af[i], bf[j]);
        }
        if (t + 1 < T) {
            sts(b ^ 1);
            if (t + 2 < T) ldg(t + 2);
        }
        __syncthreads();
    }

    // ---- epilogue: regs -> smem stage -> coalesced STG with bias / gate ----
    float* st = (float*)smem;    // 128 x 132 floats
    #pragma unroll
    for (int i = 0; i < 4; i++) {
        #pragma unroll
        for (int j = 0; j < 4; j++) {
            int row = warp_m + i * 16 + lr;
            int col = warp_n + j * 8 + 2 * kc;
            *(float2*)&st[row * 132 + col]       = make_float2(acc[i][j][0], acc[i][j][1]);
            *(float2*)&st[(row + 8) * 132 + col] = make_float2(acc[i][j][2], acc[i][j][3]);
        }
    }
    __syncthreads();
    {
        int r  = tid >> 1;
        int ch = (tid & 1) * 64;
        int grow = row0 + r;
        if (grow < M) {
            #pragma unroll
            for (int c4 = 0; c4 < 16; c4++) {
                int col = ch + c4 * 4;
                float4 v  = *(float4*)&st[r * 132 + col];
                float4 bv = *(const float4*)(bias + col0 + col);
                v.x += bv.x; v.y += bv.y; v.z += bv.z; v.w += bv.w;
                size_t idx = (size_t)grow * N + col0 + col;
                if (MODE == 1) {
                    float4 av  = *(const float4*)(ea + idx);
                    float4 a1v = *(const float4*)(eb + idx);
                    float4 o; float al;
                    al = 1.f/(1.f + __expf(-v.x)); o.x = a1v.x + al*(av.x - a1v.x);
                    al = 1.f/(1.f + __expf(-v.y)); o.y = a1v.y + al*(av.y - a1v.y);
                    al = 1.f/(1.f + __expf(-v.z)); o.z = a1v.z + al*(av.z - a1v.z);
                    al = 1.f/(1.f + __expf(-v.w)); o.w = a1v.w + al*(av.w - a1v.w);
                    *(float4*)(C + idx) = o;
                } else {
                    *(float4*)(C + idx) = v;
                }
            }
        }
    }
}

// =================== fp16 split-3 flash attention (m16n8k16), ~fp32 accuracy ===================
// 128 q-rows/CTA, 8 warps x 16 q-rows, 64-key chunks. NO 1/sqrt(d) scaling.
// K smem: [key][d] half2, row stride 36 words (72 halves). V smem transposed: [d][key] half2,
// row stride 36 words. QK D-frag feeds PV A-frag directly (FA2 identity) — no shuffles.
__global__ __launch_bounds__(256, 2)
void attn_h16(const float* __restrict__ qbase, const float* __restrict__ kbase,
              const float* __restrict__ vbase, float* __restrict__ outbuf,
              int kv_len, int q_stride, int kv_stride,
              long long q_bstride, long long kv_bstride)
{
    extern __shared__ uint32_t sm4[];
    uint32_t* Khi = sm4;                 // [64][36] words
    uint32_t* Klo = sm4 + 64*36;
    uint32_t* Vhi = sm4 + 2*64*36;       // transposed [d=64][36] words (half2 over key pairs)
    uint32_t* Vlo = sm4 + 3*64*36;

    const int tid = threadIdx.x;
    const int w = tid >> 5, lane = tid & 31;
    const int lr = lane >> 2, kc = lane & 3;
    const int h = blockIdx.y, b = blockIdx.z;
    const int q0 = blockIdx.x * 128;
    const float* qb = qbase + (size_t)b * q_bstride  + h * 64;
    const float* kb = kbase + (size_t)b * kv_bstride + h * 64;
    const float* vb = vbase + (size_t)b * kv_bstride + h * 64;

    const int qrow0 = q0 + w * 16 + lr;

    // persistent Q fragments (fp16 hi/lo), chunk c covers d = 16c..16c+15
    uint32_t Qh[4][4], Ql[4][4];
    {
        const float* r0p = qb + (size_t)qrow0 * q_stride;
        const float* r1p = qb + (size_t)(qrow0 + 8) * q_stride;
        #pragma unroll
        for (int c = 0; c < 4; c++) {
            int d0 = c * 16 + 2 * kc;
            float2 v00 = *(const float2*)(r0p + d0);
            float2 v10 = *(const float2*)(r1p + d0);
            float2 v01 = *(const float2*)(r0p + d0 + 8);
            float2 v11 = *(const float2*)(r1p + d0 + 8);
            split2h(v00.x, v00.y, Qh[c][0], Ql[c][0]);
            split2h(v10.x, v10.y, Qh[c][1], Ql[c][1]);
            split2h(v01.x, v01.y, Qh[c][2], Ql[c][2]);
            split2h(v11.x, v11.y, Qh[c][3], Ql[c][3]);
        }
    }

    float m0 = -1e30f, m1 = -1e30f, l0 = 0.f, l1 = 0.f;
    float O[8][4];
    #pragma unroll
    for (int d = 0; d < 8; d++) { O[d][0]=0.f; O[d][1]=0.f; O[d][2]=0.f; O[d][3]=0.f; }

    const int nkb = (kv_len + 63) >> 6;
    for (int t = 0; t < nkb; ++t) {
        __syncthreads();
        // ---- K loader: [key][d] half2 hi/lo ----
        {
            int key = tid >> 2, dseg = tid & 3;
            int kg = t * 64 + key;
            bool vld = kg < kv_len;
            const float* ks = kb + (size_t)kg * kv_stride + dseg * 16;
            uint32_t* kh = Khi + key * 36 + dseg * 8;
            uint32_t* kl = Klo + key * 36 + dseg * 8;
            #pragma unroll
            for (int i = 0; i < 4; i++) {
                float4 kk = vld ? *(const float4*)(ks + i*4) : make_float4(0.f,0.f,0.f,0.f);
                uint32_t h0,l0r,h1,l1r;
                split2h(kk.x, kk.y, h0, l0r);
                split2h(kk.z, kk.w, h1, l1r);
                *(uint2*)(kh + 2*i) = make_uint2(h0, h1);
                *(uint2*)(kl + 2*i) = make_uint2(l0r, l1r);
            }
        }
        // ---- V loader: transpose into [d][keypair] half2 hi/lo ----
        {
            int kp = tid & 31, dgrp = tid >> 5;   // dgrp 0..7, d = 8*dgrp + j
            int kg0 = t * 64 + 2 * kp;
            bool v0v = kg0 < kv_len, v1v = (kg0 + 1) < kv_len;
            const float* p0 = vb + (size_t)kg0 * kv_stride + dgrp * 8;
            const float* p1 = p0 + kv_stride;
            float4 x0 = v0v ? *(const float4*)(p0)     : make_float4(0.f,0.f,0.f,0.f);
            float4 x1 = v0v ? *(const float4*)(p0 + 4) : make_float4(0.f,0.f,0.f,0.f);
            float4 y0 = v1v ? *(const float4*)(p1)     : make_float4(0.f,0.f,0.f,0.f);
            float4 y1 = v1v ? *(const float4*)(p1 + 4) : make_float4(0.f,0.f,0.f,0.f);
            float xs[8] = {x0.x,x0.y,x0.z,x0.w,x1.x,x1.y,x1.z,x1.w};
            float ys[8] = {y0.x,y0.y,y0.z,y0.w,y1.x,y1.y,y1.z,y1.w};
            #pragma unroll
            for (int j = 0; j < 8; j++) {
                uint32_t hi, lo;
                split2h(xs[j], ys[j], hi, lo);
                Vhi[(dgrp*8 + j) * 36 + kp] = hi;
                Vlo[(dgrp*8 + j) * 36 + kp] = lo;
            }
        }
        __syncthreads();

        // ---- S = Q K^T (fp16 split-3) ----
        float sD[8][4];
        #pragma unroll
        for (int nt = 0; nt < 8; nt++) {
            float d4[4] = {0.f, 0.f, 0.f, 0.f};
            const int base = (8*nt + lr) * 36 + kc;
            #pragma unroll
            for (int c = 0; c < 4; c++) {
                uint32_t bh[2], bl[2];
                bh[0] = Khi[base + 8*c];  bh[1] = Khi[base + 8*c + 4];
                bl[0] = Klo[base + 8*c];  bl[1] = Klo[base + 8*c + 4];
                mma_f16(d4, Qh[c], bh);
                mma_f16(d4, Ql[c], bh);
                mma_f16(d4, Qh[c], bl);
            }
            sD[nt][0]=d4[0]; sD[nt][1]=d4[1]; sD[nt][2]=d4[2]; sD[nt][3]=d4[3];
        }

        // ---- mask partial chunk ----
        int rem = kv_len - t * 64;
        if (rem < 64) {
            #pragma unroll
            for (int nt = 0; nt < 8; nt++) {
                int k0e = 8*nt + 2*kc;
                if (k0e     >= rem) { sD[nt][0] = -1e30f; sD[nt][2] = -1e30f; }
                if (k0e + 1 >= rem) { sD[nt][1] = -1e30f; sD[nt][3] = -1e30f; }
            }
        }

        // ---- online softmax (register + quad-shfl) ----
        float rm0 = -1e30f, rm1 = -1e30f;
        #pragma unroll
        for (int nt = 0; nt < 8; nt++) {
            rm0 = fmaxf(rm0, fmaxf(sD[nt][0], sD[nt][1]));
            rm1 = fmaxf(rm1, fmaxf(sD[nt][2], sD[nt][3]));
        }
        rm0 = fmaxf(rm0, __shfl_xor_sync(0xffffffffu, rm0, 1));
        rm0 = fmaxf(rm0, __shfl_xor_sync(0xffffffffu, rm0, 2));
        rm1 = fmaxf(rm1, __shfl_xor_sync(0xffffffffu, rm1, 1));
        rm1 = fmaxf(rm1, __shfl_xor_sync(0xffffffffu, rm1, 2));
        float mn0 = fmaxf(m0, rm0), mn1 = fmaxf(m1, rm1);
        float sc0 = __expf(m0 - mn0), sc1 = __expf(m1 - mn1);
        m0 = mn0; m1 = mn1;
        float rs0 = 0.f, rs1 = 0.f;
        #pragma unroll
        for (int nt = 0; nt < 8; nt++) {
            sD[nt][0] = __expf(sD[nt][0] - m0);
            sD[nt][1] = __expf(sD[nt][1] - m0);
            sD[nt][2] = __expf(sD[nt][2] - m1);
            sD[nt][3] = __expf(sD[nt][3] - m1);
            rs0 += sD[nt][0] + sD[nt][1];
            rs1 += sD[nt][2] + sD[nt][3];
        }
        rs0 += __shfl_xor_sync(0xffffffffu, rs0, 1);
        rs0 += __shfl_xor_sync(0xffffffffu, rs0, 2);
        rs1 += __shfl_xor_sync(0xffffffffu, rs1, 1);
        rs1 += __shfl_xor_sync(0xffffffffu, rs1, 2);
        l0 = l0 * sc0 + rs0;
        l1 = l1 * sc1 + rs1;
        #pragma unroll
        for (int d = 0; d < 8; d++) {
            O[d][0] *= sc0; O[d][1] *= sc0; O[d][2] *= sc1; O[d][3] *= sc1;
        }

        // ---- O += P V (fp16 split-3); QK D-frag == PV A-frag layout, no shuffles ----
        #pragma unroll
        for (int c = 0; c < 4; c++) {
            uint32_t aH[4], aL[4];
            split2h(sD[2*c][0],   sD[2*c][1],   aH[0], aL[0]);   // rows lr,   keys 16c+2kc..+1
            split2h(sD[2*c][2],   sD[2*c][3],   aH[1], aL[1]);   // rows lr+8, keys 16c+2kc..+1
            split2h(sD[2*c+1][0], sD[2*c+1][1], aH[2], aL[2]);   // rows lr,   keys 16c+8+2kc..
            split2h(sD[2*c+1][2], sD[2*c+1][3], aH[3], aL[3]);   // rows lr+8, keys 16c+8+2kc..
            #pragma unroll
            for (int dt = 0; dt < 8; dt++) {
                const int base = (8*dt + lr) * 36 + 8*c + kc;
                uint32_t bh[2], bl[2];
                bh[0] = Vhi[base];  bh[1] = Vhi[base + 4];
                bl[0] = Vlo[base];  bl[1] = Vlo[base + 4];
                mma_f16(O[dt], aH, bh);
                mma_f16(O[dt], aL, bh);
                mma_f16(O[dt], aH, bl);
            }
        }
    }

    // ---- epilogue ----
    float inv0 = 1.f / l0, inv1 = 1.f / l1;
    float* op0 = outbuf + ((size_t)b * SEQ + qrow0) * NSTATE + h * 64;
    float* op1 = op0 + 8 * NSTATE;
    #pragma unroll
    for (int dt = 0; dt < 8; dt++) {
        *(float2*)(op0 + dt*8 + 2*kc) = make_float2(O[dt][0]*inv0, O[dt][1]*inv0);
        *(float2*)(op1 + dt*8 + 2*kc) = make_float2(O[dt][2]*inv1, O[dt][3]*inv1);
    }
}

// ------------------------------- launch --------------------------------------------
extern "C" void kernel_launch(void* const* d_in, const int* in_sizes, int n_in,
                              void* d_out, int out_size)
{
    const float* x       = (const float*)d_in[0];
    const float* w_attn  = (const float*)d_in[1];
    const float* b_attn  = (const float*)d_in[2];
    const float* w_proj  = (const float*)d_in[3];
    const float* b_proj  = (const float*)d_in[4];
    const float* w_mem   = (const float*)d_in[5];
    const float* b_mem   = (const float*)d_in[6];
    const float* w_alpha = (const float*)d_in[7];
    const float* b_alpha = (const float*)d_in[8];
    const float* memf    = (const float*)d_in[9];
    float* out = (float*)d_out;

    float *qkv, *mkv, *a, *a1, *fu, *wattnT, *wmemT, *walphaT, *wprojT;
    cudaGetSymbolAddress((void**)&qkv, g_qkv);
    cudaGetSymbolAddress((void**)&mkv, g_mkv);
    cudaGetSymbolAddress((void**)&a,   g_a);
    cudaGetSymbolAddress((void**)&a1,  g_a1);
    cudaGetSymbolAddress((void**)&fu,  g_fused);
    cudaGetSymbolAddress((void**)&wattnT,  g_wattnT);
    cudaGetSymbolAddress((void**)&wmemT,   g_wmemT);
    cudaGetSymbolAddress((void**)&walphaT, g_walphaT);
    cudaGetSymbolAddress((void**)&wprojT,  g_wprojT);

    const int attn_smem = 4 * 64 * 36 * 4;     // 36864
    const int gemm_smem = 73728;
    cudaFuncSetAttribute(attn_h16, cudaFuncAttributeMaxDynamicSharedMemorySize, attn_smem);
    cudaFuncSetAttribute(gemm_mma<0>, cudaFuncAttributeMaxDynamicSharedMemorySize, gemm_smem);
    cudaFuncSetAttribute(gemm_mma<1>, cudaFuncAttributeMaxDynamicSharedMemorySize, gemm_smem);

    dim3 tb(32, 8);
    transpose_k<<<dim3(3*NSTATE/32, NSTATE/32), tb>>>(w_attn,  wattnT,  NSTATE,   3*NSTATE);
    transpose_k<<<dim3(2*NSTATE/32, NSTATE/32), tb>>>(w_mem,   wmemT,   NSTATE,   2*NSTATE);
    transpose_k<<<dim3(NSTATE/32, 2*NSTATE/32), tb>>>(w_alpha, walphaT, 2*NSTATE, NSTATE);
    transpose_k<<<dim3(NSTATE/32, NSTATE/32),   tb>>>(w_proj,  wprojT,  NSTATE,   NSTATE);

    // 1) qkv = x @ w_attn + b_attn      [4096, 2304]
    gemm_mma<0><<<dim3(3*NSTATE/128, NTOK/128), 256, gemm_smem>>>(
        x, nullptr, wattnT, b_attn, qkv, nullptr, nullptr,
        NTOK, 3*NSTATE, NSTATE, NSTATE, 0);

    // 2) mkv = mem @ w_mem + b_mem      [100, 1536]
    gemm_mma<0><<<dim3(2*NSTATE/128, 1), 256, gemm_smem>>>(
        memf, nullptr, wmemT, b_mem, mkv, nullptr, nullptr,
        MSLOTS, 2*NSTATE, NSTATE, NSTATE, 0);

    // 3) self attention -> g_a
    attn_h16<<<dim3(SEQ/128, NHEAD, BSZ), 256, attn_smem>>>(
        qkv, qkv + NSTATE, qkv + 2*NSTATE, a,
        SEQ, 3*NSTATE, 3*NSTATE,
        (long long)SEQ * 3 * NSTATE, (long long)SEQ * 3 * NSTATE);

    // 4) memory attention -> g_a1 (kv shared across batch)
    attn_h16<<<dim3(SEQ/128, NHEAD, BSZ), 256, attn_smem>>>(
        qkv, mkv, mkv + NSTATE, a1,
        MSLOTS, 3*NSTATE, 2*NSTATE,
        (long long)SEQ * 3 * NSTATE, 0LL);

    // 5) fused = sigmoid([a|a1]@w_alpha + b_alpha) gate
    gemm_mma<1><<<dim3(NSTATE/128, NTOK/128), 256, gemm_smem>>>(
        a, a1, walphaT, b_alpha, fu, a, a1,
        NTOK, NSTATE, 2*NSTATE, NSTATE, NSTATE);

    // 6) out = fused @ w_proj + b_proj
    gemm_mma<0><<<dim3(NSTATE/128, NTOK/128), 256, gemm_smem>>>(
        fu, nullptr, wprojT, b_proj, out, nullptr, nullptr,
        NTOK, NSTATE, NSTATE, NSTATE, 0);
}

// round 11
// speedup vs baseline: 2.7160x; 1.0621x over previous
#include <cuda_runtime.h>
#include <cuda_fp16.h>
#include <cstdint>

#define NSTATE 768
#define BSZ 2
#define SEQ 2048
#define NTOK (BSZ*SEQ)        // 4096
#define NHEAD 12
#define DHEAD 64
#define MSLOTS 100
#define MPAD 128

// ---------------- scratch (device globals; no allocations allowed) ----------------
__device__ float g_qkv[NTOK * 3 * NSTATE];     // [4096, 2304]
__device__ float g_mkv[MSLOTS * 2 * NSTATE];   // [100, 1536]
__device__ float g_a   [NTOK * NSTATE];        // self-attn out
__device__ float g_a1  [NTOK * NSTATE];        // memory-attn out
__device__ float g_fused[NTOK * NSTATE];       // gated fusion
// transposed weights (K-major, N-major rows: Bt[n][k])
__device__ float g_wattnT [3*NSTATE*NSTATE];
__device__ float g_wmemT  [2*NSTATE*NSTATE];
__device__ float g_walphaT[NSTATE*2*NSTATE];
__device__ float g_wprojT [NSTATE*NSTATE];
// pre-split fp16 hi/lo K and transposed V buffers for attention
__device__ __half g_khi [BSZ*NHEAD*SEQ*DHEAD];   // [b,h,s,d]
__device__ __half g_klo [BSZ*NHEAD*SEQ*DHEAD];
__device__ __half g_vthi[BSZ*NHEAD*DHEAD*SEQ];   // [b,h,d,s]
__device__ __half g_vtlo[BSZ*NHEAD*DHEAD*SEQ];
__device__ __half g_mkhi [NHEAD*MPAD*DHEAD];     // [h,slot,d], zero-padded to 128 slots
__device__ __half g_mklo [NHEAD*MPAD*DHEAD];
__device__ __half g_mvthi[NHEAD*DHEAD*MPAD];     // [h,d,slot]
__device__ __half g_mvtlo[NHEAD*DHEAD*MPAD];

// =================== helpers (compute_103-safe only) ===================
__device__ __forceinline__ uint32_t smem_u32(const void* p){
    uint32_t a;
    asm("{ .reg .u64 t; cvta.to.shared.u64 t, %1; cvt.u32.u64 %0, t; }" : "=r"(a) : "l"(p));
    return a;
}
__device__ __forceinline__ void cp16h(uint32_t dst, const __half* src){
    asm volatile("cp.async.cg.shared.global [%0], [%1], 16;" :: "r"(dst), "l"(src));
}
template<int N> __device__ __forceinline__ void cp_wait(){
    asm volatile("cp.async.wait_group %0;" :: "n"(N) : "memory");
}
__device__ __forceinline__ void cp_commit(){
    asm volatile("cp.async.commit_group;" ::: "memory");
}
__device__ __forceinline__ uint32_t f2tf32(float f){
    uint32_t r;
    asm("cvt.rna.tf32.f32 %0, %1;" : "=r"(r) : "f"(f));
    return r;
}
__device__ __forceinline__ void mma_tf32(float* d, const uint32_t* a, const uint32_t* b){
    asm volatile("mma.sync.aligned.m16n8k8.row.col.f32.tf32.tf32.f32 "
        "{%0,%1,%2,%3}, {%4,%5,%6,%7}, {%8,%9}, {%0,%1,%2,%3};"
        : "+f"(d[0]), "+f"(d[1]), "+f"(d[2]), "+f"(d[3])
        : "r"(a[0]), "r"(a[1]), "r"(a[2]), "r"(a[3]), "r"(b[0]), "r"(b[1]));
}
__device__ __forceinline__ void mma_f16(float* d, const uint32_t* a, const uint32_t* b){
    asm volatile("mma.sync.aligned.m16n8k16.row.col.f32.f16.f16.f32 "
        "{%0,%1,%2,%3}, {%4,%5,%6,%7}, {%8,%9}, {%0,%1,%2,%3};"
        : "+f"(d[0]), "+f"(d[1]), "+f"(d[2]), "+f"(d[3])
        : "r"(a[0]), "r"(a[1]), "r"(a[2]), "r"(a[3]), "r"(b[0]), "r"(b[1]));
}
// split (x,y) into packed half2 hi and half2 lo (residual)
__device__ __forceinline__ void split2h(float x, float y, uint32_t& hi, uint32_t& lo){
    __half hx = __float2half_rn(x);
    __half hy = __float2half_rn(y);
    __half lx = __float2half_rn(x - __half2float(hx));
    __half ly = __float2half_rn(y - __half2float(hy));
    hi = (uint32_t)__half_as_ushort(hx) | ((uint32_t)__half_as_ushort(hy) << 16);
    lo = (uint32_t)__half_as_ushort(lx) | ((uint32_t)__half_as_ushort(ly) << 16);
}
__device__ __forceinline__ void split1h(float x, __half& hi, __half& lo){
    hi = __float2half_rn(x);
    lo = __float2half_rn(x - __half2float(hi));
}

// =================== weight transpose: src[K][N] -> dst[N][K] ===================
__global__ __launch_bounds__(256)
void transpose_k(const float* __restrict__ src, float* __restrict__ dst, int K, int N)
{
    __shared__ float tile[32][33];
    const int tx = threadIdx.x, ty = threadIdx.y;
    const int n0 = blockIdx.x * 32, k0 = blockIdx.y * 32;
    #pragma unroll
    for (int r = 0; r < 4; r++)
        tile[ty + r*8][tx] = src[(size_t)(k0 + ty + r*8) * N + n0 + tx];
    __syncthreads();
    #pragma unroll
    for (int r = 0; r < 4; r++)
        dst[(size_t)(n0 + ty + r*8) * K + k0 + tx] = tile[tx][ty + r*8];
}

// =================== K prep: qkv K-part -> khi/klo [b,h,s,d] half ===================
__global__ __launch_bounds__(256)
void prep_k(const float* __restrict__ qkv, __half* __restrict__ khi, __half* __restrict__ klo)
{
    int idx = blockIdx.x * 256 + threadIdx.x;        // one float4
    int flat = idx * 4;                               // element in [NTOK x 768]
    int tok = flat / NSTATE;
    int c   = flat - tok * NSTATE;
    float4 v = *(const float4*)(qkv + (size_t)tok * (3*NSTATE) + NSTATE + c);
    int b = tok >> 11, s = tok & 2047;
    int h = c >> 6,  d = c & 63;
    size_t dst = (((size_t)(b*NHEAD + h) * SEQ) + s) * DHEAD + d;
    __half h0,l0,h1,l1,h2,l2,h3,l3;
    split1h(v.x,h0,l0); split1h(v.y,h1,l1); split1h(v.z,h2,l2); split1h(v.w,h3,l3);
    ushort4 hv = make_ushort4(__half_as_ushort(h0),__half_as_ushort(h1),__half_as_ushort(h2),__half_as_ushort(h3));
    ushort4 lv = make_ushort4(__half_as_ushort(l0),__half_as_ushort(l1),__half_as_ushort(l2),__half_as_ushort(l3));
    *(ushort4*)(khi + dst) = hv;
    *(ushort4*)(klo + dst) = lv;
}

// =================== V prep: qkv V-part -> transposed vthi/vtlo [b,h,d,s] half ===================
__global__ __launch_bounds__(256)
void prep_vt(const float* __restrict__ qkv, __half* __restrict__ vthi, __half* __restrict__ vtlo)
{
    __shared__ float tile[32][33];
    const int tx = threadIdx.x, ty = threadIdx.y;
    const int s0 = blockIdx.x * 32, d0 = blockIdx.y * 32;
    const int bh = blockIdx.z;                       // b*NHEAD + h
    const int b = bh / NHEAD, h = bh - b * NHEAD;
    #pragma unroll
    for (int r = 0; r < 4; r++) {
        int s = s0 + ty + r*8;
        tile[ty + r*8][tx] = qkv[((size_t)(b*SEQ + s)) * (3*NSTATE) + 2*NSTATE + h*64 + d0 + tx];
    }
    __syncthreads();
    #pragma unroll
    for (int r = 0; r < 4; r++) {
        int d = d0 + ty + r*8;
        float v = tile[tx][ty + r*8];
        __half hi, lo; split1h(v, hi, lo);
        size_t dst = ((size_t)(bh*DHEAD + d)) * SEQ + s0 + tx;
        vthi[dst] = hi;
        vtlo[dst] = lo;
    }
}

// =================== memory-KV prep (tiny, zero-padded to 128 slots) ===================
__global__ __launch_bounds__(256)
void prep_m(const float* __restrict__ mkv,
            __half* __restrict__ mkhi, __half* __restrict__ mklo,
            __half* __restrict__ mvthi, __half* __restrict__ mvtlo)
{
    int idx = blockIdx.x * 256 + threadIdx.x;        // over NHEAD*MPAD*DHEAD
    if (idx >= NHEAD*MPAD*DHEAD) return;
    int h = idx / (MPAD*DHEAD);
    int r = idx - h * (MPAD*DHEAD);
    int slot = r >> 6, d = r & 63;
    float kvl = (slot < MSLOTS) ? mkv[(size_t)slot * (2*NSTATE) + h*64 + d] : 0.f;
    float vvl = (slot < MSLOTS) ? mkv[(size_t)slot * (2*NSTATE) + NSTATE + h*64 + d] : 0.f;
    __half khf, klf, vhf, vlf;
    split1h(kvl, khf, klf);
    split1h(vvl, vhf, vlf);
    mkhi[(size_t)(h*MPAD + slot)*DHEAD + d] = khf;
    mklo[(size_t)(h*MPAD + slot)*DHEAD + d] = klf;
    mvthi[(size_t)(h*DHEAD + d)*MPAD + slot] = vhf;
    mvtlo[(size_t)(h*DHEAD + d)*MPAD + slot] = vlf;
}

// =================== mma.sync tf32 GEMM, cvt hoisted to STS time (unchanged R7) ===================
template<int MODE>
__global__ __launch_bounds__(256)
void gemm_mma(const float* __restrict__ A, const float* __restrict__ A2,
              const float* __restrict__ Bt, const float* __restrict__ bias,
              float* __restrict__ C, const float* __restrict__ ea, const float* __restrict__ eb,
              int M, int N, int K, int lda, int ksplit)
{
    extern __shared__ char smem[];
    uint32_t* usm = (uint32_t*)smem;
    const int tid = threadIdx.x;
    const int w = tid >> 5, lane = tid & 31;
    const int lr = lane >> 2, kc = lane & 3;
    const int warp_m = (w >> 2) * 64;
    const int warp_n = (w & 3) * 32;
    const int row0 = blockIdx.y * 128, col0 = blockIdx.x * 128;

    const int T = K >> 5;
    const int arow = tid >> 1;
    const int acol0 = (tid & 1) * 16;
    const bool aval = (row0 + arow) < M;

    float4 pa[4], pb[4];
    auto ldg = [&](int t){
        int k0 = t * 32;
        const float* As; int ka;
        if (MODE == 1 && k0 >= ksplit) { As = A2; ka = k0 - ksplit; } else { As = A; ka = k0; }
        const float* asrc = As + (size_t)(row0 + arow) * lda + ka + acol0;
        const float* bsrc = Bt + (size_t)(col0 + arow) * K + k0 + acol0;
        #pragma unroll
        for (int j = 0; j < 4; j++) {
            pa[j] = aval ? *(const float4*)(asrc + 4*j) : make_float4(0.f,0.f,0.f,0.f);
            pb[j] = *(const float4*)(bsrc + 4*j);
        }
    };
    auto sts = [&](int b){
        uint32_t* da = usm + b * 4608 + arow * 36 + acol0;
        uint32_t* db = usm + 9216 + b * 4608 + arow * 36 + acol0;
        #pragma unroll
        for (int j = 0; j < 4; j++) {
            *(uint4*)(da + 4*j) = make_uint4(f2tf32(pa[j].x), f2tf32(pa[j].y), f2tf32(pa[j].z), f2tf32(pa[j].w));
            *(uint4*)(db + 4*j) = make_uint4(f2tf32(pb[j].x), f2tf32(pb[j].y), f2tf32(pb[j].z), f2tf32(pb[j].w));
        }
    };

    float acc[4][4][4];
    #pragma unroll
    for (int i = 0; i < 4; i++)
        #pragma unroll
        for (int j = 0; j < 4; j++)
            #pragma unroll
            for (int r = 0; r < 4; r++) acc[i][j][r] = 0.f;

    ldg(0); sts(0);
    if (T > 1) ldg(1);
    __syncthreads();

    for (int t = 0; t < T; ++t) {
        int b = t & 1;
        const uint32_t* Asb = usm + b * 4608;
        const uint32_t* Bsb = usm + 9216 + b * 4608;
        #pragma unroll
        for (int ks = 0; ks < 4; ks++) {
            const int kbase = ks * 8 + kc;
            uint32_t af[4][4], bf[4][2];
            #pragma unroll
            for (int i = 0; i < 4; i++) {
                int r0 = (warp_m + i * 16 + lr) * 36;
                af[i][0] = Asb[r0 + kbase];
                af[i][1] = Asb[r0 + 8*36 + kbase];
                af[i][2] = Asb[r0 + kbase + 4];
                af[i][3] = Asb[r0 + 8*36 + kbase + 4];
            }
            #pragma unroll
            for (int j = 0; j < 4; j++) {
                int r0 = (warp_n + j * 8 + lr) * 36;
                bf[j][0] = Bsb[r0 + kbase];
                bf[j][1] = Bsb[r0 + kbase + 4];
            }
            #pragma unroll
            for (int i = 0; i < 4; i++)
                #pragma unroll
                for (int j = 0; j < 4; j++)
                    mma_tf32(acc[i][j], af[i], bf[j]);
        }
        if (t + 1 < T) {
            sts(b ^ 1);
            if (t + 2 < T) ldg(t + 2);
        }
        __syncthreads();
    }

    float* st = (float*)smem;    // 128 x 132 floats
    #pragma unroll
    for (int i = 0; i < 4; i++) {
        #pragma unroll
        for (int j = 0; j < 4; j++) {
            int row = warp_m + i * 16 + lr;
            int col = warp_n + j * 8 + 2 * kc;
            *(float2*)&st[row * 132 + col]       = make_float2(acc[i][j][0], acc[i][j][1]);
            *(float2*)&st[(row + 8) * 132 + col] = make_float2(acc[i][j][2], acc[i][j][3]);
        }
    }
    __syncthreads();
    {
        int r  = tid >> 1;
        int ch = (tid & 1) * 64;
        int grow = row0 + r;
        if (grow < M) {
            #pragma unroll
            for (int c4 = 0; c4 < 16; c4++) {
                int col = ch + c4 * 4;
                float4 v  = *(float4*)&st[r * 132 + col];
                float4 bv = *(const float4*)(bias + col0 + col);
                v.x += bv.x; v.y += bv.y; v.z += bv.z; v.w += bv.w;
                size_t idx = (size_t)grow * N + col0 + col;
                if (MODE == 1) {
                    float4 av  = *(const float4*)(ea + idx);
                    float4 a1v = *(const float4*)(eb + idx);
                    float4 o; float al;
                    al = 1.f/(1.f + __expf(-v.x)); o.x = a1v.x + al*(av.x - a1v.x);
                    al = 1.f/(1.f + __expf(-v.y)); o.y = a1v.y + al*(av.y - a1v.y);
                    al = 1.f/(1.f + __expf(-v.z)); o.z = a1v.z + al*(av.z - a1v.z);
                    al = 1.f/(1.f + __expf(-v.w)); o.w = a1v.w + al*(av.w - a1v.w);
                    *(float4*)(C + idx) = o;
                } else {
                    *(float4*)(C + idx) = v;
                }
            }
        }
    }
}

// =================== fp16 split-3 flash attention, pre-split K/V via cp.async ===================
// 128 q-rows/CTA, 8 warps x 16 q-rows, 64-key chunks. NO 1/sqrt(d) scaling.
// smem tiles: rows of 36 words (32 data + 4 pad). K [key][d-half2], V transposed [d][key-half2].
// QK D-frag feeds PV A-frag directly (FA2 identity) — no shuffles.
__global__ __launch_bounds__(256, 2)
void attn_h16(const float* __restrict__ qbase,
              const __half* __restrict__ khi, const __half* __restrict__ klo,
              const __half* __restrict__ vthi, const __half* __restrict__ vtlo,
              float* __restrict__ outbuf,
              int kv_len, int kslots, int q_stride, long long q_bstride, int kv_batched)
{
    extern __shared__ uint32_t sm4[];
    uint32_t* Khi = sm4;                 // [64][36] words
    uint32_t* Klo = sm4 + 64*36;
    uint32_t* Vhi = sm4 + 2*64*36;       // [d=64][36] words (half2 over key pairs)
    uint32_t* Vlo = sm4 + 3*64*36;
    const uint32_t sb = smem_u32(sm4);

    const int tid = threadIdx.x;
    const int w = tid >> 5, lane = tid & 31;
    const int lr = lane >> 2, kc = lane & 3;
    const int h = blockIdx.y, b = blockIdx.z;
    const int q0 = blockIdx.x * 128;
    const float* qb = qbase + (size_t)b * q_bstride + h * 64;
    const int bh = kv_batched * b * NHEAD + h;
    const __half* kbh = khi  + (size_t)bh * kslots * DHEAD;
    const __half* kbl = klo  + (size_t)bh * kslots * DHEAD;
    const __half* vbh = vthi + (size_t)bh * DHEAD * kslots;
    const __half* vbl = vtlo + (size_t)bh * DHEAD * kslots;

    const int qrow0 = q0 + w * 16 + lr;

    // persistent Q fragments (fp16 hi/lo), chunk c covers d = 16c..16c+15
    uint32_t Qh[4][4], Ql[4][4];
    {
        const float* r0p = qb + (size_t)qrow0 * q_stride;
        const float* r1p = qb + (size_t)(qrow0 + 8) * q_stride;
        #pragma unroll
        for (int c = 0; c < 4; c++) {
            int d0 = c * 16 + 2 * kc;
            float2 v00 = *(const float2*)(r0p + d0);
            float2 v10 = *(const float2*)(r1p + d0);
            float2 v01 = *(const float2*)(r0p + d0 + 8);
            float2 v11 = *(const float2*)(r1p + d0 + 8);
            split2h(v00.x, v00.y, Qh[c][0], Ql[c][0]);
            split2h(v10.x, v10.y, Qh[c][1], Ql[c][1]);
            split2h(v01.x, v01.y, Qh[c][2], Ql[c][2]);
            split2h(v11.x, v11.y, Qh[c][3], Ql[c][3]);
        }
    }

    float m0 = -1e30f, m1 = -1e30f, l0 = 0.f, l1 = 0.f;
    float O[8][4];
    #pragma unroll
    for (int d = 0; d < 8; d++) { O[d][0]=0.f; O[d][1]=0.f; O[d][2]=0.f; O[d][3]=0.f; }

    // per-thread loader coordinates: row 0..63, two 16B chunks (seg, seg+1) of 8 per row
    const int ldrow = tid >> 2;
    const int ldseg = (tid & 3) * 2;
    const uint32_t soff = (uint32_t)ldrow * 144u + (uint32_t)ldseg * 16u;

    const int nkb = (kv_len + 63) >> 6;
    for (int t = 0; t < nkb; ++t) {
        __syncthreads();   // prior iter's frag reads done before overwrite
        {
            size_t goff = ((size_t)(t*64 + ldrow)) * DHEAD + ldseg * 8;   // halves
            size_t voff = ((size_t)ldrow) * kslots + (size_t)t*64 + ldseg * 8;
            cp16h(sb + soff,                    kbh + goff);
            cp16h(sb + soff + 16,               kbh + goff + 8);
            cp16h(sb + 9216u  + soff,           kbl + goff);
            cp16h(sb + 9216u  + soff + 16,      kbl + goff + 8);
            cp16h(sb + 18432u + soff,           vbh + voff);
            cp16h(sb + 18432u + soff + 16,      vbh + voff + 8);
            cp16h(sb + 27648u + soff,           vbl + voff);
            cp16h(sb + 27648u + soff + 16,      vbl + voff + 8);
            cp_commit();
        }
        cp_wait<0>();
        __syncthreads();

        // ---- S = Q K^T (fp16 split-3) ----
        float sD[8][4];
        #pragma unroll
        for (int nt = 0; nt < 8; nt++) {
            float d4[4] = {0.f, 0.f, 0.f, 0.f};
            const int base = (8*nt + lr) * 36 + kc;
            #pragma unroll
            for (int c = 0; c < 4; c++) {
                uint32_t bh2[2], bl2[2];
                bh2[0] = Khi[base + 8*c];  bh2[1] = Khi[base + 8*c + 4];
                bl2[0] = Klo[base + 8*c];  bl2[1] = Klo[base + 8*c + 4];
                mma_f16(d4, Qh[c], bh2);
                mma_f16(d4, Ql[c], bh2);
                mma_f16(d4, Qh[c], bl2);
            }
            sD[nt][0]=d4[0]; sD[nt][1]=d4[1]; sD[nt][2]=d4[2]; sD[nt][3]=d4[3];
        }

        // ---- mask partial chunk ----
        int rem = kv_len - t * 64;
        if (rem < 64) {
            #pragma unroll
            for (int nt = 0; nt < 8; nt++) {
                int k0e = 8*nt + 2*kc;
                if (k0e     >= rem) { sD[nt][0] = -1e30f; sD[nt][2] = -1e30f; }
                if (k0e + 1 >= rem) { sD[nt][1] = -1e30f; sD[nt][3] = -1e30f; }
            }
        }

        // ---- online softmax (register + quad-shfl) ----
        float rm0 = -1e30f, rm1 = -1e30f;
        #pragma unroll
        for (int nt = 0; nt < 8; nt++) {
            rm0 = fmaxf(rm0, fmaxf(sD[nt][0], sD[nt][1]));
            rm1 = fmaxf(rm1, fmaxf(sD[nt][2], sD[nt][3]));
        }
        rm0 = fmaxf(rm0, __shfl_xor_sync(0xffffffffu, rm0, 1));
        rm0 = fmaxf(rm0, __shfl_xor_sync(0xffffffffu, rm0, 2));
        rm1 = fmaxf(rm1, __shfl_xor_sync(0xffffffffu, rm1, 1));
        rm1 = fmaxf(rm1, __shfl_xor_sync(0xffffffffu, rm1, 2));
        float mn0 = fmaxf(m0, rm0), mn1 = fmaxf(m1, rm1);
        float sc0 = __expf(m0 - mn0), sc1 = __expf(m1 - mn1);
        m0 = mn0; m1 = mn1;
        float rs0 = 0.f, rs1 = 0.f;
        #pragma unroll
        for (int nt = 0; nt < 8; nt++) {
            sD[nt][0] = __expf(sD[nt][0] - m0);
            sD[nt][1] = __expf(sD[nt][1] - m0);
            sD[nt][2] = __expf(sD[nt][2] - m1);
            sD[nt][3] = __expf(sD[nt][3] - m1);
            rs0 += sD[nt][0] + sD[nt][1];
            rs1 += sD[nt][2] + sD[nt][3];
        }
        rs0 += __shfl_xor_sync(0xffffffffu, rs0, 1);
        rs0 += __shfl_xor_sync(0xffffffffu, rs0, 2);
        rs1 += __shfl_xor_sync(0xffffffffu, rs1, 1);
        rs1 += __shfl_xor_sync(0xffffffffu, rs1, 2);
        l0 = l0 * sc0 + rs0;
        l1 = l1 * sc1 + rs1;
        #pragma unroll
        for (int d = 0; d < 8; d++) {
            O[d][0] *= sc0; O[d][1] *= sc0; O[d][2] *= sc1; O[d][3] *= sc1;
        }

        // ---- O += P V (fp16 split-3); QK D-frag == PV A-frag layout, no shuffles ----
        #pragma unroll
        for (int c = 0; c < 4; c++) {
            uint32_t aH[4], aL[4];
            split2h(sD[2*c][0],   sD[2*c][1],   aH[0], aL[0]);
            split2h(sD[2*c][2],   sD[2*c][3],   aH[1], aL[1]);
            split2h(sD[2*c+1][0], sD[2*c+1][1], aH[2], aL[2]);
            split2h(sD[2*c+1][2], sD[2*c+1][3], aH[3], aL[3]);
            #pragma unroll
            for (int dt = 0; dt < 8; dt++) {
                const int base = (8*dt + lr) * 36 + 8*c + kc;
                uint32_t bh2[2], bl2[2];
                bh2[0] = Vhi[base];  bh2[1] = Vhi[base + 4];
                bl2[0] = Vlo[base];  bl2[1] = Vlo[base + 4];
                mma_f16(O[dt], aH, bh2);
                mma_f16(O[dt], aL, bh2);
                mma_f16(O[dt], aH, bl2);
            }
        }
    }

    // ---- epilogue ----
    float inv0 = 1.f / l0, inv1 = 1.f / l1;
    float* op0 = outbuf + ((size_t)b * SEQ + qrow0) * NSTATE + h * 64;
    float* op1 = op0 + 8 * NSTATE;
    #pragma unroll
    for (int dt = 0; dt < 8; dt++) {
        *(float2*)(op0 + dt*8 + 2*kc) = make_float2(O[dt][0]*inv0, O[dt][1]*inv0);
        *(float2*)(op1 + dt*8 + 2*kc) = make_float2(O[dt][2]*inv1, O[dt][3]*inv1);
    }
}

// ------------------------------- launch --------------------------------------------
extern "C" void kernel_launch(void* const* d_in, const int* in_sizes, int n_in,
                              void* d_out, int out_size)
{
    const float* x       = (const float*)d_in[0];
    const float* w_attn  = (const float*)d_in[1];
    const float* b_attn  = (const float*)d_in[2];
    const float* w_proj  = (const float*)d_in[3];
    const float* b_proj  = (const float*)d_in[4];
    const float* w_mem   = (const float*)d_in[5];
    const float* b_mem   = (const float*)d_in[6];
    const float* w_alpha = (const float*)d_in[7];
    const float* b_alpha = (const float*)d_in[8];
    const float* memf    = (const float*)d_in[9];
    float* out = (float*)d_out;

    float *qkv, *mkv, *a, *a1, *fu, *wattnT, *wmemT, *walphaT, *wprojT;
    __half *khi, *klo, *vthi, *vtlo, *mkhi, *mklo, *mvthi, *mvtlo;
    cudaGetSymbolAddress((void**)&qkv, g_qkv);
    cudaGetSymbolAddress((void**)&mkv, g_mkv);
    cudaGetSymbolAddress((void**)&a,   g_a);
    cudaGetSymbolAddress((void**)&a1,  g_a1);
    cudaGetSymbolAddress((void**)&fu,  g_fused);
    cudaGetSymbolAddress((void**)&wattnT,  g_wattnT);
    cudaGetSymbolAddress((void**)&wmemT,   g_wmemT);
    cudaGetSymbolAddress((void**)&walphaT, g_walphaT);
    cudaGetSymbolAddress((void**)&wprojT,  g_wprojT);
    cudaGetSymbolAddress((void**)&khi,  g_khi);
    cudaGetSymbolAddress((void**)&klo,  g_klo);
    cudaGetSymbolAddress((void**)&vthi, g_vthi);
    cudaGetSymbolAddress((void**)&vtlo, g_vtlo);
    cudaGetSymbolAddress((void**)&mkhi,  g_mkhi);
    cudaGetSymbolAddress((void**)&mklo,  g_mklo);
    cudaGetSymbolAddress((void**)&mvthi, g_mvthi);
    cudaGetSymbolAddress((void**)&mvtlo, g_mvtlo);

    const int attn_smem = 4 * 64 * 36 * 4;     // 36864
    const int gemm_smem = 73728;
    cudaFuncSetAttribute(attn_h16, cudaFuncAttributeMaxDynamicSharedMemorySize, attn_smem);
    cudaFuncSetAttribute(gemm_mma<0>, cudaFuncAttributeMaxDynamicSharedMemorySize, gemm_smem);
    cudaFuncSetAttribute(gemm_mma<1>, cudaFuncAttributeMaxDynamicSharedMemorySize, gemm_smem);

    dim3 tb(32, 8);
    transpose_k<<<dim3(3*NSTATE/32, NSTATE/32), tb>>>(w_attn,  wattnT,  NSTATE,   3*NSTATE);
    transpose_k<<<dim3(2*NSTATE/32, NSTATE/32), tb>>>(w_mem,   wmemT,   NSTATE,   2*NSTATE);
    transpose_k<<<dim3(NSTATE/32, 2*NSTATE/32), tb>>>(w_alpha, walphaT, 2*NSTATE, NSTATE);
    transpose_k<<<dim3(NSTATE/32, NSTATE/32),   tb>>>(w_proj,  wprojT,  NSTATE,   NSTATE);

    // 1) qkv = x @ w_attn + b_attn      [4096, 2304]
    gemm_mma<0><<<dim3(3*NSTATE/128, NTOK/128), 256, gemm_smem>>>(
        x, nullptr, wattnT, b_attn, qkv, nullptr, nullptr,
        NTOK, 3*NSTATE, NSTATE, NSTATE, 0);

    // 2) mkv = mem @ w_mem + b_mem      [100, 1536]
    gemm_mma<0><<<dim3(2*NSTATE/128, 1), 256, gemm_smem>>>(
        memf, nullptr, wmemT, b_mem, mkv, nullptr, nullptr,
        MSLOTS, 2*NSTATE, NSTATE, NSTATE, 0);

    // 2b) pre-split K/V into fp16 hi/lo buffers
    prep_k<<<NTOK*NSTATE/4/256, 256>>>(qkv, khi, klo);
    prep_vt<<<dim3(SEQ/32, DHEAD/32, BSZ*NHEAD), tb>>>(qkv, vthi, vtlo);
    prep_m<<<(NHEAD*MPAD*DHEAD + 255)/256, 256>>>(mkv, mkhi, mklo, mvthi, mvtlo);

    // 3) self attention -> g_a
    attn_h16<<<dim3(SEQ/128, NHEAD, BSZ), 256, attn_smem>>>(
        qkv, khi, klo, vthi, vtlo, a,
        SEQ, SEQ, 3*NSTATE, (long long)SEQ * 3 * NSTATE, 1);

    // 4) memory attention -> g_a1 (kv shared across batch)
    attn_h16<<<dim3(SEQ/128, NHEAD, BSZ), 256, attn_smem>>>(
        qkv, mkhi, mklo, mvthi, mvtlo, a1,
        MSLOTS, MPAD, 3*NSTATE, (long long)SEQ * 3 * NSTATE, 0);

    // 5) fused = sigmoid([a|a1]@w_alpha + b_alpha) gate
    gemm_mma<1><<<dim3(NSTATE/128, NTOK/128), 256, gemm_smem>>>(
        a, a1, walphaT, b_alpha, fu, a, a1,
        NTOK, NSTATE, 2*NSTATE, NSTATE, NSTATE);

    // 6) out = fused @ w_proj + b_proj
    gemm_mma<0><<<dim3(NSTATE/128, NTOK/128), 256, gemm_smem>>>(
        fu, nullptr, wprojT, b_proj, out, nullptr, nullptr,
        NTOK, NSTATE, NSTATE, NSTATE, 0);
}